// round 3
// baseline (speedup 1.0000x reference)
#include <cuda_runtime.h>
#include <cuda_bf16.h>
#include <math.h>

#define BB   8
#define LL   2048
#define KNN  30
#define NQ   (BB*LL)           // 16384 queries
#define NF   416               // feature dim
#define NFP  448               // padded feature dim
#define NC   128               // output channels
#define EPAD 32                // padded edge count per query

// ---------------- scratch (device globals, no allocation) ----------------
__device__ float              g_atoms[NQ * 15];        // [q][atom(5)][xyz]  N,Ca,C,O,Cb
__device__ int                g_eidx [NQ * KNN];
__device__ float              g_dn   [NQ * KNN];
__device__ float              g_wT   [NFP * NC];       // transposed+padded edge_w

__constant__ int c_pa[24] = {0,2,3,4,1,1,1,1,0,0,0,4,4,3,0,2,3,4,2,3,4,2,3,2};
__constant__ int c_pb[24] = {0,2,3,4,0,2,3,4,2,3,4,2,3,2,1,1,1,1,0,0,0,4,4,3};

// ---------------- kernel A: atoms + virtual Cb ----------------
__global__ void kAtoms(const float* __restrict__ X) {
    int q = blockIdx.x * blockDim.x + threadIdx.x;
    if (q >= NQ) return;
    const float* x = X + (size_t)q * 12;
    float Nx=x[0],  Ny=x[1],  Nz=x[2];
    float Ax=x[3],  Ay=x[4],  Az=x[5];
    float Cx=x[6],  Cy=x[7],  Cz=x[8];
    float Ox=x[9],  Oy=x[10], Oz=x[11];
    float bx=Ax-Nx, by=Ay-Ny, bz=Az-Nz;      // b = Ca - N
    float cx=Cx-Ax, cy=Cy-Ay, cz=Cz-Az;      // c = C - Ca
    float ax = by*cz - bz*cy;
    float ay = bz*cx - bx*cz;
    float az = bx*cy - by*cx;
    float Bx = -0.58273431f*ax + 0.56802827f*bx - 0.54067466f*cx + Ax;
    float By = -0.58273431f*ay + 0.56802827f*by - 0.54067466f*cy + Ay;
    float Bz = -0.58273431f*az + 0.56802827f*bz - 0.54067466f*cz + Az;
    float* o = g_atoms + (size_t)q * 15;
    o[0]=Nx; o[1]=Ny; o[2]=Nz;
    o[3]=Ax; o[4]=Ay; o[5]=Az;
    o[6]=Cx; o[7]=Cy; o[8]=Cz;
    o[9]=Ox; o[10]=Oy; o[11]=Oz;
    o[12]=Bx; o[13]=By; o[14]=Bz;
}

// ---------------- kernel T: transpose edge_w [128,416] -> wT [448,128] -----
__global__ void kTrans(const float* __restrict__ ew) {
    int idx = blockIdx.x * blockDim.x + threadIdx.x;
    if (idx >= NFP * NC) return;
    int k = idx / NC, c = idx % NC;
    g_wT[idx] = (k < NF) ? ew[(size_t)c * NF + k] : 0.0f;
}

// ---------------- kernel B: kNN (top-30 smallest, index tie-break) --------
__global__ void kKnn(const float* __restrict__ mask, float* __restrict__ outIdxF) {
    __shared__ float Dv[LL];
    __shared__ unsigned long long P[LL];
    __shared__ float wmax[8];
    __shared__ unsigned long long wmin[8];

    const int q = blockIdx.x;
    const int b = q / LL;
    const int t = threadIdx.x;
    const int lane = t & 31, wid = t >> 5;

    const float mi = mask[q];
    const float* ai = g_atoms + (size_t)q * 15;
    const float cax = ai[3], cay = ai[4], caz = ai[5];

    // pass 1: distances + row max
    float lmax = 0.0f;
    for (int j = t; j < LL; j += 256) {
        const float* aj = g_atoms + ((size_t)b * LL + j) * 15;
        float dx = cax - aj[3], dy = cay - aj[4], dz = caz - aj[5];
        float d2 = dx*dx + dy*dy + dz*dz;
        float mj = mask[b * LL + j];
        float D  = mi * mj * sqrtf(d2 + 1e-6f);
        Dv[j] = D;
        lmax = fmaxf(lmax, D);
    }
    #pragma unroll
    for (int o = 16; o > 0; o >>= 1) lmax = fmaxf(lmax, __shfl_xor_sync(0xffffffffu, lmax, o));
    if (lane == 0) wmax[wid] = lmax;
    __syncthreads();
    float Dmax = wmax[0];
    #pragma unroll
    for (int w = 1; w < 8; w++) Dmax = fmaxf(Dmax, wmax[w]);

    // pass 2: adjusted distance packed with index
    for (int j = t; j < LL; j += 256) {
        float m2  = mi * mask[b * LL + j];
        float adj = Dv[j] + (1.0f - m2) * Dmax;
        P[j] = ((unsigned long long)__float_as_uint(adj) << 32) | (unsigned)j;
    }
    __syncthreads();

    // 30x argmin
    for (int k = 0; k < KNN; k++) {
        unsigned long long lmin = 0xFFFFFFFFFFFFFFFFull;
        for (int j = t; j < LL; j += 256) lmin = min(lmin, P[j]);
        #pragma unroll
        for (int o = 16; o > 0; o >>= 1) {
            unsigned long long v = __shfl_xor_sync(0xffffffffu, lmin, o);
            lmin = min(lmin, v);
        }
        if (lane == 0) wmin[wid] = lmin;
        __syncthreads();
        unsigned long long best = wmin[0];
        #pragma unroll
        for (int w = 1; w < 8; w++) best = min(best, wmin[w]);
        int j = (int)(best & 0xFFFFFFFFull);
        if (t == 0) {
            g_eidx[(size_t)q * KNN + k] = j;
            g_dn  [(size_t)q * KNN + k] = __uint_as_float((unsigned)(best >> 32));
            outIdxF[(size_t)q * KNN + k] = (float)j;
        }
        if ((j & 255) == t) P[j] = 0xFFFFFFFFFFFFFFFFull;
        __syncthreads();
    }
}

// ---------------- kernel C: features + GEMM + LayerNorm -------------------
// dyn smem: f_s[448][32] | B_s[64][128] | aj[32][15] | ai[15] | dn[32] | j[32]
__global__ void __launch_bounds__(256) kEdge(
    const int*   __restrict__ ridx,
    const int*   __restrict__ chl,
    const float* __restrict__ pos_w,
    const float* __restrict__ pos_b,
    const float* __restrict__ ln_g,
    const float* __restrict__ ln_b,
    float*       __restrict__ outE)
{
    extern __shared__ float sm[];
    float* f_s  = sm;                    // 14336
    float* B_s  = sm + NFP * EPAD;       // 8192
    float* aj   = B_s + 64 * NC;         // 480
    float* ai   = aj + EPAD * 15;        // 15
    float* dn_s = ai + 15;               // 32
    int*   j_s  = (int*)(dn_s + EPAD);   // 32

    const int t = threadIdx.x;
    const int q = blockIdx.x;
    const int b = q / LL;

    // zero padded feature rows 416..447
    for (int idx = t; idx < 32 * EPAD; idx += 256)
        f_s[(NF + (idx >> 5)) * EPAD + (idx & 31)] = 0.0f;

    if (t < EPAD) {
        if (t < KNN) {
            j_s[t]  = g_eidx[(size_t)q * KNN + t];
            dn_s[t] = g_dn [(size_t)q * KNN + t];
        } else { j_s[t] = 0; dn_s[t] = 0.0f; }
    }
    if (t < 15) ai[t] = g_atoms[(size_t)q * 15 + t];
    __syncthreads();

    // neighbor atoms
    for (int idx = t; idx < EPAD * 15; idx += 256) {
        int e = idx / 15;
        aj[idx] = g_atoms[((size_t)b * LL + j_s[e]) * 15 + (idx % 15)];
    }

    // positional features (rows 0..15)
    if (t < EPAD) {
        int e = t;
        if (e < KNN) {
            int j    = j_s[e];
            int off  = ridx[q] - ridx[b * LL + j];
            int same = (chl[q] == chl[b * LL + j]);
            int d;
            if (same) { d = off + 32; d = d < 0 ? 0 : (d > 64 ? 64 : d); }
            else d = 65;
            #pragma unroll
            for (int c = 0; c < 16; c++)
                f_s[c * EPAD + e] = __ldg(&pos_w[c * 66 + d]) + __ldg(&pos_b[c]);
        } else {
            #pragma unroll
            for (int c = 0; c < 16; c++) f_s[c * EPAD + e] = 0.0f;
        }
    }
    __syncthreads();

    // RBF features: 25 sets x 32 edges
    // mu_r = linspace(2, 22, 16)[r] = 2 + r*(20/15);  sigma = 20/16 -> *0.8
    for (int task = t; task < 25 * EPAD; task += 256) {
        int s = task >> 5, e = task & 31;
        float* dst = &f_s[(16 + s * 16) * EPAD + e];
        if (e < KNN) {
            float Dv;
            if (s == 0) Dv = dn_s[e];
            else {
                int p  = s - 1;
                int a3 = c_pa[p] * 3, b3 = c_pb[p] * 3;
                float dx = ai[a3+0] - aj[e*15 + b3+0];
                float dy = ai[a3+1] - aj[e*15 + b3+1];
                float dz = ai[a3+2] - aj[e*15 + b3+2];
                Dv = sqrtf(dx*dx + dy*dy + dz*dz + 1e-6f);
            }
            #pragma unroll
            for (int r = 0; r < 16; r++) {
                float mu = 2.0f + (20.0f / 15.0f) * (float)r;
                float u = (Dv - mu) * 0.8f;
                dst[r * EPAD] = __expf(-u * u);
            }
        } else {
            #pragma unroll
            for (int r = 0; r < 16; r++) dst[r * EPAD] = 0.0f;
        }
    }
    __syncthreads();

    // ---- register-tiled GEMM: [32 edges x 448] @ [448 x 128] ----
    const int eg = t & 7;    // edge group (4 edges)
    const int cg = t >> 3;   // channel group (4 channels)
    float acc[4][4];
    #pragma unroll
    for (int e = 0; e < 4; e++)
        #pragma unroll
        for (int c = 0; c < 4; c++) acc[e][c] = 0.0f;

    const float4* fs4 = (const float4*)f_s;
    const float4* bs4 = (const float4*)B_s;
    const float4* wg4 = (const float4*)g_wT;

    for (int k0 = 0; k0 < NFP; k0 += 64) {
        // stage weight chunk (coalesced)
        for (int v = t; v < 64 * 32; v += 256)
            ((float4*)B_s)[v] = wg4[(size_t)k0 * 32 + v];
        __syncthreads();
        #pragma unroll 4
        for (int kk = 0; kk < 64; kk++) {
            float4 fa = fs4[(k0 + kk) * 8 + eg];
            float4 wb = bs4[kk * 32 + cg];
            acc[0][0] += fa.x*wb.x; acc[0][1] += fa.x*wb.y; acc[0][2] += fa.x*wb.z; acc[0][3] += fa.x*wb.w;
            acc[1][0] += fa.y*wb.x; acc[1][1] += fa.y*wb.y; acc[1][2] += fa.y*wb.z; acc[1][3] += fa.y*wb.w;
            acc[2][0] += fa.z*wb.x; acc[2][1] += fa.z*wb.y; acc[2][2] += fa.z*wb.z; acc[2][3] += fa.z*wb.w;
            acc[3][0] += fa.w*wb.x; acc[3][1] += fa.w*wb.y; acc[3][2] += fa.w*wb.z; acc[3][3] += fa.w*wb.w;
        }
        __syncthreads();
    }

    // stash C tile into smem (reuse B_s)
    float* out_s = B_s;      // 32*128 floats
    #pragma unroll
    for (int e = 0; e < 4; e++)
        #pragma unroll
        for (int c = 0; c < 4; c++)
            out_s[(eg * 4 + e) * NC + cg * 4 + c] = acc[e][c];
    __syncthreads();

    // ---- LayerNorm + store ----
    const int lane = t & 31, wid = t >> 5;
    float ga[4], be[4];
    #pragma unroll
    for (int m = 0; m < 4; m++) { ga[m] = __ldg(&ln_g[lane + 32*m]); be[m] = __ldg(&ln_b[lane + 32*m]); }

    for (int e = wid; e < KNN; e += 8) {
        float v[4];
        #pragma unroll
        for (int m = 0; m < 4; m++) v[m] = out_s[e * NC + lane + 32*m];
        float s = v[0] + v[1] + v[2] + v[3];
        #pragma unroll
        for (int o = 16; o > 0; o >>= 1) s += __shfl_xor_sync(0xffffffffu, s, o);
        float mu = s * (1.0f / 128.0f);
        float ss = 0.0f;
        #pragma unroll
        for (int m = 0; m < 4; m++) { float d = v[m] - mu; ss += d * d; }
        #pragma unroll
        for (int o = 16; o > 0; o >>= 1) ss += __shfl_xor_sync(0xffffffffu, ss, o);
        float rstd = rsqrtf(ss * (1.0f / 128.0f) + 1e-5f);
        float* dst = outE + ((size_t)q * KNN + e) * NC + lane;
        #pragma unroll
        for (int m = 0; m < 4; m++)
            dst[32*m] = (v[m] - mu) * rstd * ga[m] + be[m];
    }
}

// ---------------- launch ----------------
extern "C" void kernel_launch(void* const* d_in, const int* in_sizes, int n_in,
                              void* d_out, int out_size) {
    const float* X      = (const float*)d_in[0];
    const float* mask   = (const float*)d_in[1];
    const int*   ridx   = (const int*)  d_in[2];
    const int*   chl    = (const int*)  d_in[3];
    const float* pos_w  = (const float*)d_in[4];
    const float* pos_b  = (const float*)d_in[5];
    const float* edge_w = (const float*)d_in[6];
    const float* ln_g   = (const float*)d_in[7];
    const float* ln_b   = (const float*)d_in[8];
    float* out = (float*)d_out;
    float* outIdxF = out + (size_t)NQ * KNN * NC;   // E_idx tail (as float)

    static int smem_set = 0;
    const int smemC = (NFP*EPAD + 64*NC + EPAD*15 + 15 + EPAD) * 4 + EPAD * 4;
    if (!smem_set) {
        cudaFuncSetAttribute(kEdge, cudaFuncAttributeMaxDynamicSharedMemorySize, smemC);
        smem_set = 1;
    }

    kAtoms<<<(NQ + 255) / 256, 256>>>(X);
    kTrans<<<(NFP * NC + 255) / 256, 256>>>(edge_w);
    kKnn<<<NQ, 256>>>(mask, outIdxF);
    kEdge<<<NQ, 256, smemC>>>(ridx, chl, pos_w, pos_b, ln_g, ln_b, out);
}

// round 10
// speedup vs baseline: 1.8850x; 1.8850x over previous
#include <cuda_runtime.h>
#include <cuda_bf16.h>
#include <math.h>
#include <stdint.h>

#define BB   8
#define LL   2048
#define KNN  30
#define NQ   (BB*LL)           // 16384 queries
#define NFR  416               // real feature dim
#define NK   448               // padded K
#define NC   128               // output channels
#define QPB  4                 // queries per CTA
#define NCHUNK 7               // K-chunks of 64
#define CHB  16384             // tile bytes (128 rows x 128B)

// smem layout (byte offsets from 1024-aligned base)
#define SM_AH   0
#define SM_AL   16384
#define SM_B    32768          // + buf*32768 ; hi at +0, lo at +16384
#define SM_MISC 98304
#define SMEM_DYN (1024 + 98304 + 10496)

// ---------------- scratch ----------------
__device__ float  g_atoms[NQ*15];
__device__ float4 g_ca[NQ];
__device__ int    g_eidx [NQ*KNN];
__device__ float  g_dn   [NQ*KNN];
__device__ uint4  g_wPack4[2*NCHUNK*(CHB/16)];   // [hi|lo][chunk][swizzled 128x128B]

__constant__ int c_pa[24] = {0,2,3,4,1,1,1,1,0,0,0,4,4,3,0,2,3,4,2,3,4,2,3,2};
__constant__ int c_pb[24] = {0,2,3,4,0,2,3,4,2,3,4,2,3,2,1,1,1,1,0,0,0,4,4,3};

// ---------------- helpers ----------------
__device__ __forceinline__ uint32_t smem_u32(const void* p){
    uint32_t a;
    asm("{ .reg .u64 t; cvta.to.shared.u64 t, %1; cvt.u32.u64 %0, t; }" : "=r"(a) : "l"(p));
    return a;
}
__device__ __forceinline__ uint32_t sw128(uint32_t off){ return off ^ ((off >> 3) & 0x70); }

__device__ __forceinline__ void ldsm_x4(uint32_t& r0, uint32_t& r1, uint32_t& r2, uint32_t& r3, uint32_t addr){
    asm volatile("ldmatrix.sync.aligned.m8n8.x4.shared.b16 {%0,%1,%2,%3}, [%4];"
                 : "=r"(r0), "=r"(r1), "=r"(r2), "=r"(r3) : "r"(addr));
}
__device__ __forceinline__ void mma16816(float* c,
    uint32_t a0, uint32_t a1, uint32_t a2, uint32_t a3, uint32_t b0, uint32_t b1){
    asm volatile("mma.sync.aligned.m16n8k16.row.col.f32.bf16.bf16.f32 "
                 "{%0,%1,%2,%3}, {%4,%5,%6,%7}, {%8,%9}, {%0,%1,%2,%3};"
                 : "+f"(c[0]), "+f"(c[1]), "+f"(c[2]), "+f"(c[3])
                 : "r"(a0), "r"(a1), "r"(a2), "r"(a3), "r"(b0), "r"(b1));
}
__device__ __forceinline__ void cp16(uint32_t dst, const void* src){
    asm volatile("cp.async.cg.shared.global [%0], [%1], 16;" :: "r"(dst), "l"(src));
}
__device__ __forceinline__ void cp_commit(){ asm volatile("cp.async.commit_group;" ::: "memory"); }
template<int N> __device__ __forceinline__ void cp_wait(){
    asm volatile("cp.async.wait_group %0;" :: "n"(N) : "memory");
}

// ---------------- kernel A: atoms + virtual Cb ----------------
__global__ void kAtoms(const float* __restrict__ X) {
    int q = blockIdx.x * blockDim.x + threadIdx.x;
    if (q >= NQ) return;
    const float* x = X + (size_t)q * 12;
    float Nx=x[0],  Ny=x[1],  Nz=x[2];
    float Ax=x[3],  Ay=x[4],  Az=x[5];
    float Cx=x[6],  Cy=x[7],  Cz=x[8];
    float Ox=x[9],  Oy=x[10], Oz=x[11];
    float bx=Ax-Nx, by=Ay-Ny, bz=Az-Nz;
    float cx=Cx-Ax, cy=Cy-Ay, cz=Cz-Az;
    float ax = by*cz - bz*cy;
    float ay = bz*cx - bx*cz;
    float az = bx*cy - by*cx;
    float Bx = -0.58273431f*ax + 0.56802827f*bx - 0.54067466f*cx + Ax;
    float By = -0.58273431f*ay + 0.56802827f*by - 0.54067466f*cy + Ay;
    float Bz = -0.58273431f*az + 0.56802827f*bz - 0.54067466f*cz + Az;
    float* o = g_atoms + (size_t)q * 15;
    o[0]=Nx; o[1]=Ny; o[2]=Nz;
    o[3]=Ax; o[4]=Ay; o[5]=Az;
    o[6]=Cx; o[7]=Cy; o[8]=Cz;
    o[9]=Ox; o[10]=Oy; o[11]=Oz;
    o[12]=Bx; o[13]=By; o[14]=Bz;
    g_ca[q] = make_float4(Ax, Ay, Az, 0.0f);
}

// ---------------- kernel W: split edge_w into swizzled bf16 hi/lo tiles ----
// layout: [chunk c][ch 0..127][k 0..63] bf16, sw128-swizzled; hi chunks 0..6, lo 7..13
__global__ void kPrepW(const float* __restrict__ ew) {
    int idx = blockIdx.x * blockDim.x + threadIdx.x;
    if (idx >= NC * NK) return;
    int ch = idx / NK, k = idx % NK;
    float v = (k < NFR) ? ew[(size_t)ch * NFR + k] : 0.0f;
    uint32_t u  = __float_as_uint(v);
    uint32_t hu = u & 0xFFFF0000u;                 // truncated hi (exact bf16)
    float lo = v - __uint_as_float(hu);            // exact residual
    __nv_bfloat16 lb = __float2bfloat16(lo);
    int c = k >> 6, kk = k & 63;
    uint32_t sw = sw128((uint32_t)(ch * 128 + kk * 2));
    unsigned char* base = (unsigned char*)g_wPack4;
    *(unsigned short*)(base + (size_t)c * CHB + sw) = (unsigned short)(hu >> 16);
    *(unsigned short*)(base + (size_t)(NCHUNK + c) * CHB + sw) = __bfloat16_as_ushort(lb);
}

// ---------------- kernel B: kNN (top-30 smallest, index tie-break) --------
__global__ void kKnn(const float* __restrict__ mask, float* __restrict__ outIdxF) {
    __shared__ float Dv[LL];
    __shared__ unsigned long long P[LL];
    __shared__ float wmax[8];
    __shared__ unsigned long long wmin[8];

    const int q = blockIdx.x;
    const int b = q / LL;
    const int t = threadIdx.x;
    const int lane = t & 31, wid = t >> 5;

    const float mi = mask[q];
    const float4 ca = g_ca[q];

    float lmax = 0.0f;
    for (int j = t; j < LL; j += 256) {
        float4 cj = g_ca[b * LL + j];
        float dx = ca.x - cj.x, dy = ca.y - cj.y, dz = ca.z - cj.z;
        float d2 = dx*dx + dy*dy + dz*dz;
        float mj = mask[b * LL + j];
        float D  = mi * mj * sqrtf(d2 + 1e-6f);
        Dv[j] = D;
        lmax = fmaxf(lmax, D);
    }
    #pragma unroll
    for (int o = 16; o > 0; o >>= 1) lmax = fmaxf(lmax, __shfl_xor_sync(0xffffffffu, lmax, o));
    if (lane == 0) wmax[wid] = lmax;
    __syncthreads();
    float Dmax = wmax[0];
    #pragma unroll
    for (int w = 1; w < 8; w++) Dmax = fmaxf(Dmax, wmax[w]);

    for (int j = t; j < LL; j += 256) {
        float m2  = mi * mask[b * LL + j];
        float adj = Dv[j] + (1.0f - m2) * Dmax;
        P[j] = ((unsigned long long)__float_as_uint(adj) << 32) | (unsigned)j;
    }
    __syncthreads();

    for (int k = 0; k < KNN; k++) {
        unsigned long long lmin = 0xFFFFFFFFFFFFFFFFull;
        for (int j = t; j < LL; j += 256) lmin = min(lmin, P[j]);
        #pragma unroll
        for (int o = 16; o > 0; o >>= 1) {
            unsigned long long v = __shfl_xor_sync(0xffffffffu, lmin, o);
            lmin = min(lmin, v);
        }
        if (lane == 0) wmin[wid] = lmin;
        __syncthreads();
        unsigned long long best = wmin[0];
        #pragma unroll
        for (int w = 1; w < 8; w++) best = min(best, wmin[w]);
        int j = (int)(best & 0xFFFFFFFFull);
        if (t == 0) {
            g_eidx[(size_t)q * KNN + k] = j;
            g_dn  [(size_t)q * KNN + k] = __uint_as_float((unsigned)(best >> 32));
            outIdxF[(size_t)q * KNN + k] = (float)j;
        }
        if ((j & 255) == t) P[j] = 0xFFFFFFFFFFFFFFFFull;
        __syncthreads();
    }
}

// ---------------- kernel C: features -> HMMA GEMM -> LayerNorm ------------
__device__ __forceinline__ void stageB(int t, int c, int buf, uint32_t base) {
    uint32_t dsth = base + SM_B + (uint32_t)buf * 32768u;
    const uint4* sh = g_wPack4 + (size_t)c * (CHB/16);
    const uint4* sl = g_wPack4 + (size_t)(NCHUNK + c) * (CHB/16);
    #pragma unroll
    for (int i = 0; i < 4; i++) {
        int idx = t + i * 256;
        cp16(dsth + (uint32_t)idx * 16u, (const void*)(sh + idx));
        cp16(dsth + 16384u + (uint32_t)idx * 16u, (const void*)(sl + idx));
    }
}

__global__ void __launch_bounds__(256, 1) kEdge(
    const int*   __restrict__ ridx,
    const int*   __restrict__ chl,
    const float* __restrict__ pos_w,
    const float* __restrict__ pos_b,
    const float* __restrict__ ln_g,
    const float* __restrict__ ln_b,
    float*       __restrict__ outE)
{
    extern __shared__ unsigned char smraw[];
    const uint32_t base0 = smem_u32(smraw);
    const uint32_t base  = (base0 + 1023u) & ~1023u;
    unsigned char* sm    = smraw + (base - base0);

    unsigned char* miscb = sm + SM_MISC;
    float* aj   = (float*)(miscb);           // 128*15 f
    float* ai   = (float*)(miscb + 7680);    // 64 f
    float* dn_s = (float*)(miscb + 7936);    // 128 f
    int*   j_s  = (int*)  (miscb + 8448);    // 128 i
    int*   didx = (int*)  (miscb + 8960);    // 128 i
    float* lng  = (float*)(miscb + 9472);    // 128 f
    float* lnb  = (float*)(miscb + 9984);    // 128 f

    const int t  = threadIdx.x;
    const int q0 = blockIdx.x * QPB;
    const int b  = q0 / LL;

    // per-edge metadata
    if (t < 128) {
        int qi = t >> 5, e = t & 31;
        int q = q0 + qi;
        if (e < KNN) {
            int j = g_eidx[(size_t)q * KNN + e];
            j_s[t]  = j;
            dn_s[t] = g_dn[(size_t)q * KNN + e];
            int off  = ridx[q] - ridx[b * LL + j];
            int same = (chl[q] == chl[b * LL + j]);
            int d;
            if (same) { d = off + 32; d = d < 0 ? 0 : (d > 64 ? 64 : d); }
            else d = 65;
            didx[t] = d;
        } else { j_s[t] = 0; dn_s[t] = 0.0f; didx[t] = 0; }
        lng[t] = ln_g[t];
        lnb[t] = ln_b[t];
    }
    if (t < 60) ai[t] = g_atoms[(size_t)(q0 + t / 15) * 15 + (t % 15)];
    __syncthreads();

    for (int idx = t; idx < 128 * 15; idx += 256) {
        int er = idx / 15;
        aj[idx] = g_atoms[((size_t)b * LL + j_s[er]) * 15 + (idx % 15)];
    }

    // prefetch B chunk 0
    stageB(t, 0, 0, base);
    cp_commit();
    __syncthreads();

    const int wid = t >> 5, lane = t & 31;
    const int wm = wid & 1, wn = wid >> 1;     // warp tile: M 2 x N 4
    const int lr = lane & 15, lh = lane >> 4;

    float acc[4][4][4];
    #pragma unroll
    for (int mt = 0; mt < 4; mt++)
        #pragma unroll
        for (int nt = 0; nt < 4; nt++)
            #pragma unroll
            for (int i = 0; i < 4; i++) acc[mt][nt][i] = 0.0f;

    unsigned char* Ah = sm + SM_AH;
    unsigned char* Al = sm + SM_AL;

    for (int c = 0; c < NCHUNK; c++) {
        const int buf = c & 1;
        if (c < 6) { stageB(t, c + 1, buf ^ 1, base); cp_commit(); }

        // ---- compute feature chunk into A (hi/lo swizzled bf16) ----
        #pragma unroll
        for (int it = 0; it < 2; it++) {
            int task = t + it * 256;            // 512 tasks: 4 groups x 128 rows
            int gl   = task >> 7, row = task & 127;
            int g    = c * 4 + gl;
            int qi   = row >> 5, e = row & 31;
            float v[16];
            bool valid = (e < KNN) && (g < 26);
            if (valid) {
                if (g == 0) {
                    int d = didx[row];
                    #pragma unroll
                    for (int r = 0; r < 16; r++)
                        v[r] = __ldg(pos_w + r * 66 + d) + __ldg(pos_b + r);
                } else {
                    float D;
                    int s = g - 1;
                    if (s == 0) D = dn_s[row];
                    else {
                        int p = s - 1;
                        int a3 = c_pa[p] * 3, b3 = c_pb[p] * 3;
                        const float* aiq = ai + qi * 15;
                        const float* ajr = aj + row * 15;
                        float dx = aiq[a3+0] - ajr[b3+0];
                        float dy = aiq[a3+1] - ajr[b3+1];
                        float dz = aiq[a3+2] - ajr[b3+2];
                        D = sqrtf(dx*dx + dy*dy + dz*dz + 1e-6f);
                    }
                    #pragma unroll
                    for (int r = 0; r < 16; r++) {
                        float u = (D - (2.0f + (20.0f/15.0f) * (float)r)) * 0.8f;
                        v[r] = __expf(-u * u);
                    }
                }
            } else {
                #pragma unroll
                for (int r = 0; r < 16; r++) v[r] = 0.0f;
            }
            uint32_t hw[8], lw[8];
            #pragma unroll
            for (int i = 0; i < 8; i++) {
                uint32_t u0 = __float_as_uint(v[2*i]);
                uint32_t u1 = __float_as_uint(v[2*i+1]);
                float l0 = v[2*i]   - __uint_as_float(u0 & 0xFFFF0000u);
                float l1 = v[2*i+1] - __uint_as_float(u1 & 0xFFFF0000u);
                hw[i] = __byte_perm(u0, u1, 0x7632);
                asm("cvt.rn.bf16x2.f32 %0, %1, %2;" : "=r"(lw[i]) : "f"(l1), "f"(l0));
            }
            uint32_t off = (uint32_t)(row * 128 + gl * 32);
            uint32_t s0 = sw128(off), s1 = sw128(off + 16);
            *(uint4*)(Ah + s0) = make_uint4(hw[0], hw[1], hw[2], hw[3]);
            *(uint4*)(Ah + s1) = make_uint4(hw[4], hw[5], hw[6], hw[7]);
            *(uint4*)(Al + s0) = make_uint4(lw[0], lw[1], lw[2], lw[3]);
            *(uint4*)(Al + s1) = make_uint4(lw[4], lw[5], lw[6], lw[7]);
        }

        if (c < 6) cp_wait<1>(); else cp_wait<0>();
        __syncthreads();

        // ---- ldmatrix + HMMA over this chunk ----
        const uint32_t Bh = base + SM_B + (uint32_t)buf * 32768u;
        const uint32_t Bl = Bh + 16384u;
        const uint32_t Ahb = base + SM_AH;
        const uint32_t Alb = base + SM_AL;

        #pragma unroll
        for (int ks = 0; ks < 4; ks++) {
            uint32_t bh[8], bl[8];
            #pragma unroll
            for (int p = 0; p < 2; p++) {
                int ch = wn * 32 + p * 16 + lr;
                uint32_t off = (uint32_t)(ch * 128 + ks * 32 + lh * 16);
                uint32_t sw = sw128(off);
                ldsm_x4(bh[p*4+0], bh[p*4+1], bh[p*4+2], bh[p*4+3], Bh + sw);
                ldsm_x4(bl[p*4+0], bl[p*4+1], bl[p*4+2], bl[p*4+3], Bl + sw);
            }
            #pragma unroll
            for (int mt = 0; mt < 4; mt++) {
                int row = wm * 64 + mt * 16 + lr;
                uint32_t off = (uint32_t)(row * 128 + ks * 32 + lh * 16);
                uint32_t sw = sw128(off);
                uint32_t a0, a1, a2, a3, l0, l1, l2, l3;
                ldsm_x4(a0, a1, a2, a3, Ahb + sw);
                ldsm_x4(l0, l1, l2, l3, Alb + sw);
                #pragma unroll
                for (int nt = 0; nt < 4; nt++) {
                    uint32_t b0 = bh[(nt >> 1) * 4 + (nt & 1)];
                    uint32_t b1 = bh[(nt >> 1) * 4 + 2 + (nt & 1)];
                    mma16816(acc[mt][nt], a0, a1, a2, a3, b0, b1);
                }
                #pragma unroll
                for (int nt = 0; nt < 4; nt++) {
                    uint32_t b0 = bl[(nt >> 1) * 4 + (nt & 1)];
                    uint32_t b1 = bl[(nt >> 1) * 4 + 2 + (nt & 1)];
                    mma16816(acc[mt][nt], a0, a1, a2, a3, b0, b1);
                }
                #pragma unroll
                for (int nt = 0; nt < 4; nt++) {
                    uint32_t b0 = bh[(nt >> 1) * 4 + (nt & 1)];
                    uint32_t b1 = bh[(nt >> 1) * 4 + 2 + (nt & 1)];
                    mma16816(acc[mt][nt], l0, l1, l2, l3, b0, b1);
                }
            }
        }
        __syncthreads();
    }

    // ---- epilogue: acc -> smem [ch][edge] (stride 132, conflict-free) ----
    float* C_s = (float*)sm;
    #pragma unroll
    for (int mt = 0; mt < 4; mt++) {
        int e0 = wm * 64 + mt * 16 + (lane >> 2);
        #pragma unroll
        for (int nt = 0; nt < 4; nt++) {
            int ch0 = wn * 32 + nt * 8 + (lane & 3) * 2;
            C_s[ch0       * 132 + e0]     = acc[mt][nt][0];
            C_s[(ch0 + 1) * 132 + e0]     = acc[mt][nt][1];
            C_s[ch0       * 132 + e0 + 8] = acc[mt][nt][2];
            C_s[(ch0 + 1) * 132 + e0 + 8] = acc[mt][nt][3];
        }
    }
    __syncthreads();

    // ---- LayerNorm + store (thread t = edge row) ----
    if (t < 128) {
        int qi = t >> 5, e = t & 31;
        if (e < KNN) {
            float v[128];
            float s = 0.0f;
            #pragma unroll
            for (int i = 0; i < 128; i++) { v[i] = C_s[i * 132 + t]; s += v[i]; }
            float mu = s * (1.0f / 128.0f);
            float ss = 0.0f;
            #pragma unroll
            for (int i = 0; i < 128; i++) { float d = v[i] - mu; ss += d * d; }
            float rstd = rsqrtf(ss * (1.0f / 128.0f) + 1e-5f);
            float4* dst = (float4*)(outE + ((size_t)(q0 + qi) * KNN + e) * NC);
            #pragma unroll
            for (int i = 0; i < 32; i++) {
                float4 o;
                o.x = (v[4*i+0] - mu) * rstd * lng[4*i+0] + lnb[4*i+0];
                o.y = (v[4*i+1] - mu) * rstd * lng[4*i+1] + lnb[4*i+1];
                o.z = (v[4*i+2] - mu) * rstd * lng[4*i+2] + lnb[4*i+2];
                o.w = (v[4*i+3] - mu) * rstd * lng[4*i+3] + lnb[4*i+3];
                dst[i] = o;
            }
        }
    }
}

// ---------------- launch ----------------
extern "C" void kernel_launch(void* const* d_in, const int* in_sizes, int n_in,
                              void* d_out, int out_size) {
    const float* X      = (const float*)d_in[0];
    const float* mask   = (const float*)d_in[1];
    const int*   ridx   = (const int*)  d_in[2];
    const int*   chl    = (const int*)  d_in[3];
    const float* pos_w  = (const float*)d_in[4];
    const float* pos_b  = (const float*)d_in[5];
    const float* edge_w = (const float*)d_in[6];
    const float* ln_g   = (const float*)d_in[7];
    const float* ln_b   = (const float*)d_in[8];
    float* out = (float*)d_out;
    float* outIdxF = out + (size_t)NQ * KNN * NC;

    static int attr_set = 0;
    if (!attr_set) {
        cudaFuncSetAttribute(kEdge, cudaFuncAttributeMaxDynamicSharedMemorySize, SMEM_DYN);
        attr_set = 1;
    }

    kAtoms<<<(NQ + 255) / 256, 256>>>(X);
    kPrepW<<<(NC * NK + 255) / 256, 256>>>(edge_w);
    kKnn<<<NQ, 256>>>(mask, outIdxF);
    kEdge<<<NQ / QPB, 256, SMEM_DYN>>>(ridx, chl, pos_w, pos_b, ln_g, ln_b, out);
}

// round 11
// speedup vs baseline: 2.9083x; 1.5428x over previous
#include <cuda_runtime.h>
#include <cuda_bf16.h>
#include <math.h>
#include <stdint.h>

#define BB   8
#define LL   2048
#define KNN  30
#define NQ   (BB*LL)           // 16384 queries
#define NFR  416               // real feature dim
#define NK   448               // padded K
#define NC   128               // output channels
#define QPB  4                 // queries per CTA
#define NCHUNK 7               // K-chunks of 64
#define CHB  16384             // tile bytes (128 rows x 128B)

// smem layout (byte offsets from 1024-aligned base)
// A: 2 bufs x (hi 16K + lo 16K) = 64K ; B: 2 bufs x (hi 16K + lo 16K) = 64K
#define SM_A    0
#define SM_B    65536
#define SM_MISC 131072
#define SMEM_DYN (1024 + 131072 + 10496)

// ---------------- scratch ----------------
__device__ float  g_atoms[NQ*15];
__device__ float4 g_ca[NQ];
__device__ int    g_eidx [NQ*KNN];
__device__ float  g_dn   [NQ*KNN];
__device__ uint4  g_wPack4[2*NCHUNK*(CHB/16)];   // [hi|lo][chunk][swizzled 128x128B]

__constant__ int c_pa[24] = {0,2,3,4,1,1,1,1,0,0,0,4,4,3,0,2,3,4,2,3,4,2,3,2};
__constant__ int c_pb[24] = {0,2,3,4,0,2,3,4,2,3,4,2,3,2,1,1,1,1,0,0,0,4,4,3};

// ---------------- helpers ----------------
__device__ __forceinline__ uint32_t smem_u32(const void* p){
    uint32_t a;
    asm("{ .reg .u64 t; cvta.to.shared.u64 t, %1; cvt.u32.u64 %0, t; }" : "=r"(a) : "l"(p));
    return a;
}
__device__ __forceinline__ uint32_t sw128(uint32_t off){ return off ^ ((off >> 3) & 0x70); }

__device__ __forceinline__ void ldsm_x4(uint32_t& r0, uint32_t& r1, uint32_t& r2, uint32_t& r3, uint32_t addr){
    asm volatile("ldmatrix.sync.aligned.m8n8.x4.shared.b16 {%0,%1,%2,%3}, [%4];"
                 : "=r"(r0), "=r"(r1), "=r"(r2), "=r"(r3) : "r"(addr));
}
__device__ __forceinline__ void mma16816(float* c,
    uint32_t a0, uint32_t a1, uint32_t a2, uint32_t a3, uint32_t b0, uint32_t b1){
    asm volatile("mma.sync.aligned.m16n8k16.row.col.f32.bf16.bf16.f32 "
                 "{%0,%1,%2,%3}, {%4,%5,%6,%7}, {%8,%9}, {%0,%1,%2,%3};"
                 : "+f"(c[0]), "+f"(c[1]), "+f"(c[2]), "+f"(c[3])
                 : "r"(a0), "r"(a1), "r"(a2), "r"(a3), "r"(b0), "r"(b1));
}
__device__ __forceinline__ void cp16(uint32_t dst, const void* src){
    asm volatile("cp.async.cg.shared.global [%0], [%1], 16;" :: "r"(dst), "l"(src));
}
__device__ __forceinline__ void cp_commit(){ asm volatile("cp.async.commit_group;" ::: "memory"); }
template<int N> __device__ __forceinline__ void cp_wait(){
    asm volatile("cp.async.wait_group %0;" :: "n"(N) : "memory");
}
__device__ __forceinline__ unsigned long long umin64(unsigned long long a, unsigned long long b){
    return a < b ? a : b;
}

// ---------------- kernel A: atoms + virtual Cb ----------------
__global__ void kAtoms(const float* __restrict__ X) {
    int q = blockIdx.x * blockDim.x + threadIdx.x;
    if (q >= NQ) return;
    const float* x = X + (size_t)q * 12;
    float Nx=x[0],  Ny=x[1],  Nz=x[2];
    float Ax=x[3],  Ay=x[4],  Az=x[5];
    float Cx=x[6],  Cy=x[7],  Cz=x[8];
    float Ox=x[9],  Oy=x[10], Oz=x[11];
    float bx=Ax-Nx, by=Ay-Ny, bz=Az-Nz;
    float cx=Cx-Ax, cy=Cy-Ay, cz=Cz-Az;
    float ax = by*cz - bz*cy;
    float ay = bz*cx - bx*cz;
    float az = bx*cy - by*cx;
    float Bx = -0.58273431f*ax + 0.56802827f*bx - 0.54067466f*cx + Ax;
    float By = -0.58273431f*ay + 0.56802827f*by - 0.54067466f*cy + Ay;
    float Bz = -0.58273431f*az + 0.56802827f*bz - 0.54067466f*cz + Az;
    float* o = g_atoms + (size_t)q * 15;
    o[0]=Nx; o[1]=Ny; o[2]=Nz;
    o[3]=Ax; o[4]=Ay; o[5]=Az;
    o[6]=Cx; o[7]=Cy; o[8]=Cz;
    o[9]=Ox; o[10]=Oy; o[11]=Oz;
    o[12]=Bx; o[13]=By; o[14]=Bz;
    g_ca[q] = make_float4(Ax, Ay, Az, 0.0f);
}

// ---------------- kernel W: split edge_w into swizzled bf16 hi/lo tiles ----
__global__ void kPrepW(const float* __restrict__ ew) {
    int idx = blockIdx.x * blockDim.x + threadIdx.x;
    if (idx >= NC * NK) return;
    int ch = idx / NK, k = idx % NK;
    float v = (k < NFR) ? ew[(size_t)ch * NFR + k] : 0.0f;
    uint32_t u  = __float_as_uint(v);
    uint32_t hu = u & 0xFFFF0000u;                 // truncated hi (exact bf16)
    float lo = v - __uint_as_float(hu);            // exact residual
    __nv_bfloat16 lb = __float2bfloat16(lo);
    int c = k >> 6, kk = k & 63;
    uint32_t sw = sw128((uint32_t)(ch * 128 + kk * 2));
    unsigned char* base = (unsigned char*)g_wPack4;
    *(unsigned short*)(base + (size_t)c * CHB + sw) = (unsigned short)(hu >> 16);
    *(unsigned short*)(base + (size_t)(NCHUNK + c) * CHB + sw) = __bfloat16_as_ushort(lb);
}

// ---------------- kernel B: hierarchical kNN ------------------------------
__global__ void kKnn(const float* __restrict__ mask, float* __restrict__ outIdxF) {
    __shared__ float Dv[LL];
    __shared__ unsigned long long P[LL];
    __shared__ unsigned long long gmin[64];
    __shared__ float wmax[8];

    const int q = blockIdx.x;
    const int b = q / LL;
    const int t = threadIdx.x;
    const int lane = t & 31, wid = t >> 5;

    const float mi = mask[q];
    const float4 ca = g_ca[q];

    // pass 1: distances + row max
    float lmax = 0.0f;
    #pragma unroll
    for (int i = 0; i < 8; i++) {
        int j = t + i * 256;
        float4 cj = g_ca[b * LL + j];
        float dx = ca.x - cj.x, dy = ca.y - cj.y, dz = ca.z - cj.z;
        float d2 = dx*dx + dy*dy + dz*dz;
        float mj = mask[b * LL + j];
        float D  = mi * mj * sqrtf(d2 + 1e-6f);
        Dv[j] = D;
        lmax = fmaxf(lmax, D);
    }
    #pragma unroll
    for (int o = 16; o > 0; o >>= 1) lmax = fmaxf(lmax, __shfl_xor_sync(0xffffffffu, lmax, o));
    if (lane == 0) wmax[wid] = lmax;
    __syncthreads();
    float Dmax = wmax[0];
    #pragma unroll
    for (int w = 1; w < 8; w++) Dmax = fmaxf(Dmax, wmax[w]);

    // pass 2: adjusted distance packed with index
    #pragma unroll
    for (int i = 0; i < 8; i++) {
        int j = t + i * 256;
        float m2  = mi * mask[b * LL + j];
        float adj = Dv[j] + (1.0f - m2) * Dmax;
        P[j] = ((unsigned long long)__float_as_uint(adj) << 32) | (unsigned)j;
    }
    __syncthreads();

    // per-group (32 elems) mins: warp w owns groups w*8 .. w*8+7
    #pragma unroll
    for (int i = 0; i < 8; i++) {
        int g = wid * 8 + i;
        unsigned long long v = P[g * 32 + lane];
        #pragma unroll
        for (int o = 16; o > 0; o >>= 1)
            v = umin64(v, __shfl_xor_sync(0xffffffffu, v, o));
        if (lane == 0) gmin[g] = v;
    }
    __syncthreads();

    // 30 extractions — warp 0 only, no block barriers
    if (wid == 0) {
        for (int k = 0; k < KNN; k++) {
            unsigned long long x = umin64(gmin[lane], gmin[lane + 32]);
            #pragma unroll
            for (int o = 16; o > 0; o >>= 1)
                x = umin64(x, __shfl_xor_sync(0xffffffffu, x, o));
            int j = (int)(x & 0xFFFFFFFFull);
            if (lane == 0) {
                g_eidx[(size_t)q * KNN + k] = j;
                g_dn  [(size_t)q * KNN + k] = __uint_as_float((unsigned)(x >> 32));
                outIdxF[(size_t)q * KNN + k] = (float)j;
            }
            int g = j >> 5;
            unsigned long long v = P[g * 32 + lane];
            if (g * 32 + lane == j) { v = 0xFFFFFFFFFFFFFFFFull; P[j] = 0xFFFFFFFFFFFFFFFFull; }
            #pragma unroll
            for (int o = 16; o > 0; o >>= 1)
                v = umin64(v, __shfl_xor_sync(0xffffffffu, v, o));
            if (lane == 0) gmin[g] = v;
            __syncwarp();
        }
    }
}

// ---------------- kernel C: features -> HMMA GEMM -> LayerNorm ------------
__device__ __forceinline__ void stageB(int t, int c, int buf, uint32_t base) {
    uint32_t dsth = base + SM_B + (uint32_t)buf * 32768u;
    const uint4* sh = g_wPack4 + (size_t)c * (CHB/16);
    const uint4* sl = g_wPack4 + (size_t)(NCHUNK + c) * (CHB/16);
    #pragma unroll
    for (int i = 0; i < 4; i++) {
        int idx = t + i * 256;
        cp16(dsth + (uint32_t)idx * 16u, (const void*)(sh + idx));
        cp16(dsth + 16384u + (uint32_t)idx * 16u, (const void*)(sl + idx));
    }
}

__global__ void __launch_bounds__(256, 1) kEdge(
    const int*   __restrict__ ridx,
    const int*   __restrict__ chl,
    const float* __restrict__ pos_w,
    const float* __restrict__ pos_b,
    const float* __restrict__ ln_g,
    const float* __restrict__ ln_b,
    float*       __restrict__ outE)
{
    extern __shared__ unsigned char smraw[];
    const uint32_t base0 = smem_u32(smraw);
    const uint32_t base  = (base0 + 1023u) & ~1023u;
    unsigned char* sm    = smraw + (base - base0);

    unsigned char* miscb = sm + SM_MISC;
    float* aj   = (float*)(miscb);           // 128*15 f
    float* ai   = (float*)(miscb + 7680);    // 64 f
    float* dn_s = (float*)(miscb + 7936);    // 128 f
    int*   j_s  = (int*)  (miscb + 8448);    // 128 i
    int*   didx = (int*)  (miscb + 8960);    // 128 i
    float* lng  = (float*)(miscb + 9472);    // 128 f
    float* lnb  = (float*)(miscb + 9984);    // 128 f

    const int t  = threadIdx.x;
    const int q0 = blockIdx.x * QPB;
    const int b  = q0 / LL;

    // per-edge metadata
    if (t < 128) {
        int qi = t >> 5, e = t & 31;
        int q = q0 + qi;
        if (e < KNN) {
            int j = g_eidx[(size_t)q * KNN + e];
            j_s[t]  = j;
            dn_s[t] = g_dn[(size_t)q * KNN + e];
            int off  = ridx[q] - ridx[b * LL + j];
            int same = (chl[q] == chl[b * LL + j]);
            int d;
            if (same) { d = off + 32; d = d < 0 ? 0 : (d > 64 ? 64 : d); }
            else d = 65;
            didx[t] = d;
        } else { j_s[t] = 0; dn_s[t] = 0.0f; didx[t] = 0; }
        lng[t] = ln_g[t];
        lnb[t] = ln_b[t];
    }
    if (t < 60) ai[t] = g_atoms[(size_t)(q0 + t / 15) * 15 + (t % 15)];
    __syncthreads();

    for (int idx = t; idx < 128 * 15; idx += 256) {
        int er = idx / 15;
        aj[idx] = g_atoms[((size_t)b * LL + j_s[er]) * 15 + (idx % 15)];
    }

    // prefetch B chunk 0 into buf 0
    stageB(t, 0, 0, base);
    cp_commit();
    __syncthreads();

    const int wid = t >> 5, lane = t & 31;
    const int wm = wid & 1, wn = wid >> 1;     // warp tile: M 2 x N 4
    const int lr = lane & 15, lh = lane >> 4;

    float acc[4][4][4];
    #pragma unroll
    for (int mt = 0; mt < 4; mt++)
        #pragma unroll
        for (int nt = 0; nt < 4; nt++)
            #pragma unroll
            for (int i = 0; i < 4; i++) acc[mt][nt][i] = 0.0f;

    // ---- feature compute lambda-ish macro via function scope loop ----
    // computes chunk cc into A buffer (abuf)
    auto computeA = [&](int cc, int abuf) {
        unsigned char* Ah = sm + SM_A + (uint32_t)abuf * 32768u;
        unsigned char* Al = Ah + 16384;
        #pragma unroll
        for (int it = 0; it < 2; it++) {
            int task = t + it * 256;            // 512 tasks: 4 groups x 128 rows
            int gl   = task >> 7, row = task & 127;
            int g    = cc * 4 + gl;
            int qi   = row >> 5, e = row & 31;
            float v[16];
            bool valid = (e < KNN) && (g < 26);
            if (valid) {
                if (g == 0) {
                    int d = didx[row];
                    #pragma unroll
                    for (int r = 0; r < 16; r++)
                        v[r] = __ldg(pos_w + r * 66 + d) + __ldg(pos_b + r);
                } else {
                    float D;
                    int s = g - 1;
                    if (s == 0) D = dn_s[row];
                    else {
                        int p = s - 1;
                        int a3 = c_pa[p] * 3, b3 = c_pb[p] * 3;
                        const float* aiq = ai + qi * 15;
                        const float* ajr = aj + row * 15;
                        float dx = aiq[a3+0] - ajr[b3+0];
                        float dy = aiq[a3+1] - ajr[b3+1];
                        float dz = aiq[a3+2] - ajr[b3+2];
                        D = sqrtf(dx*dx + dy*dy + dz*dz + 1e-6f);
                    }
                    #pragma unroll
                    for (int r = 0; r < 16; r++) {
                        float u = (D - (2.0f + (20.0f/15.0f) * (float)r)) * 0.8f;
                        v[r] = __expf(-u * u);
                    }
                }
            } else {
                #pragma unroll
                for (int r = 0; r < 16; r++) v[r] = 0.0f;
            }
            uint32_t hw[8], lw[8];
            #pragma unroll
            for (int i = 0; i < 8; i++) {
                uint32_t u0 = __float_as_uint(v[2*i]);
                uint32_t u1 = __float_as_uint(v[2*i+1]);
                float l0 = v[2*i]   - __uint_as_float(u0 & 0xFFFF0000u);
                float l1 = v[2*i+1] - __uint_as_float(u1 & 0xFFFF0000u);
                hw[i] = __byte_perm(u0, u1, 0x7632);
                asm("cvt.rn.bf16x2.f32 %0, %1, %2;" : "=r"(lw[i]) : "f"(l1), "f"(l0));
            }
            uint32_t off = (uint32_t)(row * 128 + gl * 32);
            uint32_t s0 = sw128(off), s1 = sw128(off + 16);
            *(uint4*)(Ah + s0) = make_uint4(hw[0], hw[1], hw[2], hw[3]);
            *(uint4*)(Ah + s1) = make_uint4(hw[4], hw[5], hw[6], hw[7]);
            *(uint4*)(Al + s0) = make_uint4(lw[0], lw[1], lw[2], lw[3]);
            *(uint4*)(Al + s1) = make_uint4(lw[4], lw[5], lw[6], lw[7]);
        }
    };

    // pre-loop: features for chunk 0
    computeA(0, 0);
    __syncthreads();

    for (int c = 0; c < NCHUNK; c++) {
        const int buf = c & 1;
        if (c < 6) { stageB(t, c + 1, buf ^ 1, base); cp_commit(); }
        if (c < 6) cp_wait<1>(); else cp_wait<0>();

        // ---- ldmatrix + HMMA over chunk c ----
        const uint32_t Bh  = base + SM_B + (uint32_t)buf * 32768u;
        const uint32_t Bl  = Bh + 16384u;
        const uint32_t Ahb = base + SM_A + (uint32_t)buf * 32768u;
        const uint32_t Alb = Ahb + 16384u;

        #pragma unroll
        for (int ks = 0; ks < 4; ks++) {
            uint32_t bh[8], bl[8];
            #pragma unroll
            for (int p = 0; p < 2; p++) {
                int ch = wn * 32 + p * 16 + lr;
                uint32_t off = (uint32_t)(ch * 128 + ks * 32 + lh * 16);
                uint32_t sw = sw128(off);
                ldsm_x4(bh[p*4+0], bh[p*4+1], bh[p*4+2], bh[p*4+3], Bh + sw);
                ldsm_x4(bl[p*4+0], bl[p*4+1], bl[p*4+2], bl[p*4+3], Bl + sw);
            }
            #pragma unroll
            for (int mt = 0; mt < 4; mt++) {
                int row = wm * 64 + mt * 16 + lr;
                uint32_t off = (uint32_t)(row * 128 + ks * 32 + lh * 16);
                uint32_t sw = sw128(off);
                uint32_t a0, a1, a2, a3, l0, l1, l2, l3;
                ldsm_x4(a0, a1, a2, a3, Ahb + sw);
                ldsm_x4(l0, l1, l2, l3, Alb + sw);
                #pragma unroll
                for (int nt = 0; nt < 4; nt++) {
                    uint32_t b0 = bh[(nt >> 1) * 4 + (nt & 1)];
                    uint32_t b1 = bh[(nt >> 1) * 4 + 2 + (nt & 1)];
                    mma16816(acc[mt][nt], a0, a1, a2, a3, b0, b1);
                }
                #pragma unroll
                for (int nt = 0; nt < 4; nt++) {
                    uint32_t b0 = bl[(nt >> 1) * 4 + (nt & 1)];
                    uint32_t b1 = bl[(nt >> 1) * 4 + 2 + (nt & 1)];
                    mma16816(acc[mt][nt], a0, a1, a2, a3, b0, b1);
                }
                #pragma unroll
                for (int nt = 0; nt < 4; nt++) {
                    uint32_t b0 = bh[(nt >> 1) * 4 + (nt & 1)];
                    uint32_t b1 = bh[(nt >> 1) * 4 + 2 + (nt & 1)];
                    mma16816(acc[mt][nt], l0, l1, l2, l3, b0, b1);
                }
            }
        }

        // overlap: compute features for chunk c+1 into the other A buffer
        if (c < 6) computeA(c + 1, buf ^ 1);
        __syncthreads();
    }

    // ---- epilogue: acc -> smem [ch][edge] (stride 132) ----
    float* C_s = (float*)sm;
    #pragma unroll
    for (int mt = 0; mt < 4; mt++) {
        int e0 = wm * 64 + mt * 16 + (lane >> 2);
        #pragma unroll
        for (int nt = 0; nt < 4; nt++) {
            int ch0 = wn * 32 + nt * 8 + (lane & 3) * 2;
            C_s[ch0       * 132 + e0]     = acc[mt][nt][0];
            C_s[(ch0 + 1) * 132 + e0]     = acc[mt][nt][1];
            C_s[ch0       * 132 + e0 + 8] = acc[mt][nt][2];
            C_s[(ch0 + 1) * 132 + e0 + 8] = acc[mt][nt][3];
        }
    }
    __syncthreads();

    // ---- LayerNorm + store: two-pass over smem, no register array ----
    if (t < 128) {
        int qi = t >> 5, e = t & 31;
        if (e < KNN) {
            float s = 0.0f, ss = 0.0f;
            #pragma unroll
            for (int i = 0; i < 128; i++) {
                float v = C_s[i * 132 + t];
                s += v; ss += v * v;
            }
            float mu   = s * (1.0f / 128.0f);
            float var  = ss * (1.0f / 128.0f) - mu * mu;
            float rstd = rsqrtf(var + 1e-5f);
            float4* dst = (float4*)(outE + ((size_t)(q0 + qi) * KNN + e) * NC);
            #pragma unroll
            for (int i = 0; i < 32; i++) {
                float4 o;
                o.x = (C_s[(4*i+0) * 132 + t] - mu) * rstd * lng[4*i+0] + lnb[4*i+0];
                o.y = (C_s[(4*i+1) * 132 + t] - mu) * rstd * lng[4*i+1] + lnb[4*i+1];
                o.z = (C_s[(4*i+2) * 132 + t] - mu) * rstd * lng[4*i+2] + lnb[4*i+2];
                o.w = (C_s[(4*i+3) * 132 + t] - mu) * rstd * lng[4*i+3] + lnb[4*i+3];
                dst[i] = o;
            }
        }
    }
}

// ---------------- launch ----------------
extern "C" void kernel_launch(void* const* d_in, const int* in_sizes, int n_in,
                              void* d_out, int out_size) {
    const float* X      = (const float*)d_in[0];
    const float* mask   = (const float*)d_in[1];
    const int*   ridx   = (const int*)  d_in[2];
    const int*   chl    = (const int*)  d_in[3];
    const float* pos_w  = (const float*)d_in[4];
    const float* pos_b  = (const float*)d_in[5];
    const float* edge_w = (const float*)d_in[6];
    const float* ln_g   = (const float*)d_in[7];
    const float* ln_b   = (const float*)d_in[8];
    float* out = (float*)d_out;
    float* outIdxF = out + (size_t)NQ * KNN * NC;

    static int attr_set = 0;
    if (!attr_set) {
        cudaFuncSetAttribute(kEdge, cudaFuncAttributeMaxDynamicSharedMemorySize, SMEM_DYN);
        attr_set = 1;
    }

    kAtoms<<<(NQ + 255) / 256, 256>>>(X);
    kPrepW<<<(NC * NK + 255) / 256, 256>>>(edge_w);
    kKnn<<<NQ, 256>>>(mask, outIdxF);
    kEdge<<<NQ / QPB, 256, SMEM_DYN>>>(ridx, chl, pos_w, pos_b, ln_g, ln_b, out);
}

// round 15
// speedup vs baseline: 3.1019x; 1.0666x over previous
#include <cuda_runtime.h>
#include <cuda_bf16.h>
#include <math.h>
#include <stdint.h>

#define BB   8
#define LL   2048
#define KNN  30
#define NQ   (BB*LL)           // 16384 queries
#define NFR  416               // real feature dim
#define NK   448               // padded K
#define NC   128               // output channels
#define QPB  8                 // queries per CTA -> M=256
#define MR   256               // edge rows per CTA
#define NT   512               // threads
#define NCHUNK 7               // K-chunks of 64
#define CHB  16384             // B tile bytes (128 ch x 128B)
#define AHB  32768             // A half bytes (256 rows x 128B)

// smem layout (byte offsets from 1024-aligned base)
#define SM_A    0              // 2 bufs x (hi 32K + lo 32K) = 128K
#define SM_B    131072         // 2 bufs x (hi 16K + lo 16K) = 64K
#define SM_MISC 196608
// misc sub-offsets (bytes from SM_MISC)
#define MS_AJ   0              // 256*15*4 = 15360
#define MS_AI   15360          // 120*4 -> pad 480
#define MS_DN   15840          // 256*4
#define MS_JS   16864          // 256*4
#define MS_DIDX 17888          // 256*4
#define MS_LNG  18912          // 128*4
#define MS_LNB  19424          // 128*4
#define MS_END  19936
#define SMEM_DYN (1024 + SM_MISC + MS_END)

// ---------------- scratch ----------------
__device__ float  g_atoms[NQ*15];
__device__ float4 g_ca[NQ];
__device__ int    g_eidx [NQ*KNN];
__device__ float  g_dn   [NQ*KNN];
__device__ uint4  g_wPack4[2*NCHUNK*(CHB/16)];   // [hi|lo][chunk][swizzled 128x128B]

__constant__ int c_pa[24] = {0,2,3,4,1,1,1,1,0,0,0,4,4,3,0,2,3,4,2,3,4,2,3,2};
__constant__ int c_pb[24] = {0,2,3,4,0,2,3,4,2,3,4,2,3,2,1,1,1,1,0,0,0,4,4,3};

// ---------------- helpers ----------------
__device__ __forceinline__ uint32_t smem_u32(const void* p){
    uint32_t a;
    asm("{ .reg .u64 t; cvta.to.shared.u64 t, %1; cvt.u32.u64 %0, t; }" : "=r"(a) : "l"(p));
    return a;
}
__device__ __forceinline__ uint32_t sw128(uint32_t off){ return off ^ ((off >> 3) & 0x70); }

__device__ __forceinline__ void ldsm_x4(uint32_t& r0, uint32_t& r1, uint32_t& r2, uint32_t& r3, uint32_t addr){
    asm volatile("ldmatrix.sync.aligned.m8n8.x4.shared.b16 {%0,%1,%2,%3}, [%4];"
                 : "=r"(r0), "=r"(r1), "=r"(r2), "=r"(r3) : "r"(addr));
}
__device__ __forceinline__ void mma16816(float* c,
    uint32_t a0, uint32_t a1, uint32_t a2, uint32_t a3, uint32_t b0, uint32_t b1){
    asm volatile("mma.sync.aligned.m16n8k16.row.col.f32.bf16.bf16.f32 "
                 "{%0,%1,%2,%3}, {%4,%5,%6,%7}, {%8,%9}, {%0,%1,%2,%3};"
                 : "+f"(c[0]), "+f"(c[1]), "+f"(c[2]), "+f"(c[3])
                 : "r"(a0), "r"(a1), "r"(a2), "r"(a3), "r"(b0), "r"(b1));
}
__device__ __forceinline__ void cp16(uint32_t dst, const void* src){
    asm volatile("cp.async.cg.shared.global [%0], [%1], 16;" :: "r"(dst), "l"(src));
}
__device__ __forceinline__ void cp_commit(){ asm volatile("cp.async.commit_group;" ::: "memory"); }
template<int N> __device__ __forceinline__ void cp_wait(){
    asm volatile("cp.async.wait_group %0;" :: "n"(N) : "memory");
}
__device__ __forceinline__ unsigned long long umin64(unsigned long long a, unsigned long long b){
    return a < b ? a : b;
}

// ---------------- kernel A: atoms + virtual Cb ----------------
__global__ void kAtoms(const float* __restrict__ X) {
    int q = blockIdx.x * blockDim.x + threadIdx.x;
    if (q >= NQ) return;
    const float* x = X + (size_t)q * 12;
    float Nx=x[0],  Ny=x[1],  Nz=x[2];
    float Ax=x[3],  Ay=x[4],  Az=x[5];
    float Cx=x[6],  Cy=x[7],  Cz=x[8];
    float Ox=x[9],  Oy=x[10], Oz=x[11];
    float bx=Ax-Nx, by=Ay-Ny, bz=Az-Nz;
    float cx=Cx-Ax, cy=Cy-Ay, cz=Cz-Az;
    float ax = by*cz - bz*cy;
    float ay = bz*cx - bx*cz;
    float az = bx*cy - by*cx;
    float Bx = -0.58273431f*ax + 0.56802827f*bx - 0.54067466f*cx + Ax;
    float By = -0.58273431f*ay + 0.56802827f*by - 0.54067466f*cy + Ay;
    float Bz = -0.58273431f*az + 0.56802827f*bz - 0.54067466f*cz + Az;
    float* o = g_atoms + (size_t)q * 15;
    o[0]=Nx; o[1]=Ny; o[2]=Nz;
    o[3]=Ax; o[4]=Ay; o[5]=Az;
    o[6]=Cx; o[7]=Cy; o[8]=Cz;
    o[9]=Ox; o[10]=Oy; o[11]=Oz;
    o[12]=Bx; o[13]=By; o[14]=Bz;
    g_ca[q] = make_float4(Ax, Ay, Az, 0.0f);
}

// ---------------- kernel W: split edge_w into swizzled bf16 hi/lo tiles ----
__global__ void kPrepW(const float* __restrict__ ew) {
    int idx = blockIdx.x * blockDim.x + threadIdx.x;
    if (idx >= NC * NK) return;
    int ch = idx / NK, k = idx % NK;
    float v = (k < NFR) ? ew[(size_t)ch * NFR + k] : 0.0f;
    uint32_t u  = __float_as_uint(v);
    uint32_t hu = u & 0xFFFF0000u;                 // truncated hi (exact bf16)
    float lo = v - __uint_as_float(hu);            // exact residual
    __nv_bfloat16 lb = __float2bfloat16(lo);
    int c = k >> 6, kk = k & 63;
    uint32_t sw = sw128((uint32_t)(ch * 128 + kk * 2));
    unsigned char* base = (unsigned char*)g_wPack4;
    *(unsigned short*)(base + (size_t)c * CHB + sw) = (unsigned short)(hu >> 16);
    *(unsigned short*)(base + (size_t)(NCHUNK + c) * CHB + sw) = __bfloat16_as_ushort(lb);
}

// ---------------- kernel B: hierarchical kNN ------------------------------
__global__ void kKnn(const float* __restrict__ mask, float* __restrict__ outIdxF) {
    __shared__ float Dv[LL];
    __shared__ unsigned long long P[LL];
    __shared__ unsigned long long gmin[64];
    __shared__ float wmax[8];

    const int q = blockIdx.x;
    const int b = q / LL;
    const int t = threadIdx.x;
    const int lane = t & 31, wid = t >> 5;

    const float mi = mask[q];
    const float4 ca = g_ca[q];

    float lmax = 0.0f;
    #pragma unroll
    for (int i = 0; i < 8; i++) {
        int j = t + i * 256;
        float4 cj = g_ca[b * LL + j];
        float dx = ca.x - cj.x, dy = ca.y - cj.y, dz = ca.z - cj.z;
        float d2 = dx*dx + dy*dy + dz*dz;
        float mj = mask[b * LL + j];
        float D  = mi * mj * sqrtf(d2 + 1e-6f);
        Dv[j] = D;
        lmax = fmaxf(lmax, D);
    }
    #pragma unroll
    for (int o = 16; o > 0; o >>= 1) lmax = fmaxf(lmax, __shfl_xor_sync(0xffffffffu, lmax, o));
    if (lane == 0) wmax[wid] = lmax;
    __syncthreads();
    float Dmax = wmax[0];
    #pragma unroll
    for (int w = 1; w < 8; w++) Dmax = fmaxf(Dmax, wmax[w]);

    #pragma unroll
    for (int i = 0; i < 8; i++) {
        int j = t + i * 256;
        float m2  = mi * mask[b * LL + j];
        float adj = Dv[j] + (1.0f - m2) * Dmax;
        P[j] = ((unsigned long long)__float_as_uint(adj) << 32) | (unsigned)j;
    }
    __syncthreads();

    #pragma unroll
    for (int i = 0; i < 8; i++) {
        int g = wid * 8 + i;
        unsigned long long v = P[g * 32 + lane];
        #pragma unroll
        for (int o = 16; o > 0; o >>= 1)
            v = umin64(v, __shfl_xor_sync(0xffffffffu, v, o));
        if (lane == 0) gmin[g] = v;
    }
    __syncthreads();

    if (wid == 0) {
        for (int k = 0; k < KNN; k++) {
            unsigned long long x = umin64(gmin[lane], gmin[lane + 32]);
            #pragma unroll
            for (int o = 16; o > 0; o >>= 1)
                x = umin64(x, __shfl_xor_sync(0xffffffffu, x, o));
            int j = (int)(x & 0xFFFFFFFFull);
            if (lane == 0) {
                g_eidx[(size_t)q * KNN + k] = j;
                g_dn  [(size_t)q * KNN + k] = __uint_as_float((unsigned)(x >> 32));
                outIdxF[(size_t)q * KNN + k] = (float)j;
            }
            int g = j >> 5;
            unsigned long long v = P[g * 32 + lane];
            if (g * 32 + lane == j) { v = 0xFFFFFFFFFFFFFFFFull; P[j] = 0xFFFFFFFFFFFFFFFFull; }
            #pragma unroll
            for (int o = 16; o > 0; o >>= 1)
                v = umin64(v, __shfl_xor_sync(0xffffffffu, v, o));
            if (lane == 0) gmin[g] = v;
            __syncwarp();
        }
    }
}

// ---------------- kernel C: features -> HMMA GEMM -> LayerNorm ------------
__device__ __forceinline__ void stageB(int t, int c, int buf, uint32_t base) {
    uint32_t dsth = base + SM_B + (uint32_t)buf * 32768u;
    const uint4* sh = g_wPack4 + (size_t)c * (CHB/16);
    const uint4* sl = g_wPack4 + (size_t)(NCHUNK + c) * (CHB/16);
    #pragma unroll
    for (int i = 0; i < 2; i++) {
        int idx = t + i * NT;
        cp16(dsth + (uint32_t)idx * 16u, (const void*)(sh + idx));
        cp16(dsth + 16384u + (uint32_t)idx * 16u, (const void*)(sl + idx));
    }
}

__global__ void __launch_bounds__(NT, 1) kEdge(
    const int*   __restrict__ ridx,
    const int*   __restrict__ chl,
    const float* __restrict__ pos_w,
    const float* __restrict__ pos_b,
    const float* __restrict__ ln_g,
    const float* __restrict__ ln_b,
    float*       __restrict__ outE)
{
    extern __shared__ unsigned char smraw[];
    const uint32_t base0 = smem_u32(smraw);
    const uint32_t base  = (base0 + 1023u) & ~1023u;
    unsigned char* sm    = smraw + (base - base0);

    unsigned char* miscb = sm + SM_MISC;
    float* aj   = (float*)(miscb + MS_AJ);
    float* ai   = (float*)(miscb + MS_AI);
    float* dn_s = (float*)(miscb + MS_DN);
    int*   j_s  = (int*)  (miscb + MS_JS);
    int*   didx = (int*)  (miscb + MS_DIDX);
    float* lng  = (float*)(miscb + MS_LNG);
    float* lnb  = (float*)(miscb + MS_LNB);

    const int t  = threadIdx.x;
    const int q0 = blockIdx.x * QPB;
    const int b  = q0 / LL;

    // per-edge metadata (256 rows)
    if (t < MR) {
        int qi = t >> 5, e = t & 31;
        int q = q0 + qi;
        if (e < KNN) {
            int j = g_eidx[(size_t)q * KNN + e];
            j_s[t]  = j;
            dn_s[t] = g_dn[(size_t)q * KNN + e];
            int off  = ridx[q] - ridx[b * LL + j];
            int same = (chl[q] == chl[b * LL + j]);
            int d;
            if (same) { d = off + 32; d = d < 0 ? 0 : (d > 64 ? 64 : d); }
            else d = 65;
            didx[t] = d;
        } else { j_s[t] = 0; dn_s[t] = 0.0f; didx[t] = 0; }
    }
    if (t >= 256 && t < 384) { lng[t - 256] = ln_g[t - 256]; lnb[t - 256] = ln_b[t - 256]; }
    if (t >= 384 && t < 384 + QPB * 15) {
        int u = t - 384;
        ai[u] = g_atoms[(size_t)(q0 + u / 15) * 15 + (u % 15)];
    }
    __syncthreads();

    for (int idx = t; idx < MR * 15; idx += NT) {
        int er = idx / 15;
        aj[idx] = g_atoms[((size_t)b * LL + j_s[er]) * 15 + (idx % 15)];
    }

    // prefetch B chunk 0 into buf 0
    stageB(t, 0, 0, base);
    cp_commit();
    __syncthreads();

    const int wid = t >> 5, lane = t & 31;
    const int wm = wid & 3, wn = wid >> 2;     // warp grid: 4M x 4N
    const int lr = lane & 15, lh = lane >> 4;

    float acc[4][4][4];
    #pragma unroll
    for (int mt = 0; mt < 4; mt++)
        #pragma unroll
        for (int nt = 0; nt < 4; nt++)
            #pragma unroll
            for (int i = 0; i < 4; i++) acc[mt][nt][i] = 0.0f;

    // feature chunk cc -> A buffer abuf (256 rows x 64 K as hi/lo bf16, swizzled)
    auto computeA = [&](int cc, int abuf) {
        unsigned char* Ah = sm + SM_A + (uint32_t)abuf * 65536u;
        unsigned char* Al = Ah + AHB;
        #pragma unroll
        for (int it = 0; it < 2; it++) {
            int task = t + it * NT;             // 1024 tasks: 4 groups x 256 rows
            int gl   = task >> 8, row = task & 255;
            int g    = cc * 4 + gl;
            int qi   = row >> 5, e = row & 31;
            float v[16];
            bool valid = (e < KNN) && (g < 26);
            if (valid) {
                if (g == 0) {
                    int d = didx[row];
                    #pragma unroll
                    for (int r = 0; r < 16; r++)
                        v[r] = __ldg(pos_w + r * 66 + d) + __ldg(pos_b + r);
                } else {
                    float D;
                    int s = g - 1;
                    if (s == 0) D = dn_s[row];
                    else {
                        int p = s - 1;
                        int a3 = c_pa[p] * 3, b3 = c_pb[p] * 3;
                        const float* aiq = ai + qi * 15;
                        const float* ajr = aj + row * 15;
                        float dx = aiq[a3+0] - ajr[b3+0];
                        float dy = aiq[a3+1] - ajr[b3+1];
                        float dz = aiq[a3+2] - ajr[b3+2];
                        D = sqrtf(dx*dx + dy*dy + dz*dz + 1e-6f);
                    }
                    #pragma unroll
                    for (int r = 0; r < 16; r++) {
                        float u = (D - (2.0f + (20.0f/15.0f) * (float)r)) * 0.8f;
                        v[r] = __expf(-u * u);
                    }
                }
            } else {
                #pragma unroll
                for (int r = 0; r < 16; r++) v[r] = 0.0f;
            }
            uint32_t hw[8], lw[8];
            #pragma unroll
            for (int i = 0; i < 8; i++) {
                uint32_t u0 = __float_as_uint(v[2*i]);
                uint32_t u1 = __float_as_uint(v[2*i+1]);
                float l0 = v[2*i]   - __uint_as_float(u0 & 0xFFFF0000u);
                float l1 = v[2*i+1] - __uint_as_float(u1 & 0xFFFF0000u);
                hw[i] = __byte_perm(u0, u1, 0x7632);
                asm("cvt.rn.bf16x2.f32 %0, %1, %2;" : "=r"(lw[i]) : "f"(l1), "f"(l0));
            }
            uint32_t off = (uint32_t)(row * 128 + gl * 32);
            uint32_t s0 = sw128(off), s1 = sw128(off + 16);
            *(uint4*)(Ah + s0) = make_uint4(hw[0], hw[1], hw[2], hw[3]);
            *(uint4*)(Ah + s1) = make_uint4(hw[4], hw[5], hw[6], hw[7]);
            *(uint4*)(Al + s0) = make_uint4(lw[0], lw[1], lw[2], lw[3]);
            *(uint4*)(Al + s1) = make_uint4(lw[4], lw[5], lw[6], lw[7]);
        }
    };

    computeA(0, 0);
    __syncthreads();

    for (int c = 0; c < NCHUNK; c++) {
        const int buf = c & 1;
        if (c < 6) { stageB(t, c + 1, buf ^ 1, base); cp_commit(); }
        if (c < 6) cp_wait<1>(); else cp_wait<0>();

        const uint32_t Bh  = base + SM_B + (uint32_t)buf * 32768u;
        const uint32_t Bl  = Bh + 16384u;
        const uint32_t Ahb = base + SM_A + (uint32_t)buf * 65536u;
        const uint32_t Alb = Ahb + AHB;

        #pragma unroll
        for (int ks = 0; ks < 4; ks++) {
            uint32_t bh[8], bl[8];
            #pragma unroll
            for (int p = 0; p < 2; p++) {
                int ch = wn * 32 + p * 16 + lr;
                uint32_t off = (uint32_t)(ch * 128 + ks * 32 + lh * 16);
                uint32_t sw = sw128(off);
                ldsm_x4(bh[p*4+0], bh[p*4+1], bh[p*4+2], bh[p*4+3], Bh + sw);
                ldsm_x4(bl[p*4+0], bl[p*4+1], bl[p*4+2], bl[p*4+3], Bl + sw);
            }
            #pragma unroll
            for (int mt = 0; mt < 4; mt++) {
                int row = wm * 64 + mt * 16 + lr;
                uint32_t off = (uint32_t)(row * 128 + ks * 32 + lh * 16);
                uint32_t sw = sw128(off);
                uint32_t a0, a1, a2, a3, l0, l1, l2, l3;
                ldsm_x4(a0, a1, a2, a3, Ahb + sw);
                ldsm_x4(l0, l1, l2, l3, Alb + sw);
                #pragma unroll
                for (int nt = 0; nt < 4; nt++) {
                    uint32_t b0 = bh[(nt >> 1) * 4 + (nt & 1)];
                    uint32_t b1 = bh[(nt >> 1) * 4 + 2 + (nt & 1)];
                    mma16816(acc[mt][nt], a0, a1, a2, a3, b0, b1);
                }
                #pragma unroll
                for (int nt = 0; nt < 4; nt++) {
                    uint32_t b0 = bl[(nt >> 1) * 4 + (nt & 1)];
                    uint32_t b1 = bl[(nt >> 1) * 4 + 2 + (nt & 1)];
                    mma16816(acc[mt][nt], a0, a1, a2, a3, b0, b1);
                }
                #pragma unroll
                for (int nt = 0; nt < 4; nt++) {
                    uint32_t b0 = bh[(nt >> 1) * 4 + (nt & 1)];
                    uint32_t b1 = bh[(nt >> 1) * 4 + 2 + (nt & 1)];
                    mma16816(acc[mt][nt], l0, l1, l2, l3, b0, b1);
                }
            }
        }

        if (c < 6) computeA(c + 1, buf ^ 1);
        __syncthreads();
    }

    // ---- epilogue: acc -> smem [ch][edge] stride 260 (conflict-free) ----
    float* C_s = (float*)sm;
    #pragma unroll
    for (int mt = 0; mt < 4; mt++) {
        int e0 = wm * 64 + mt * 16 + (lane >> 2);
        #pragma unroll
        for (int nt = 0; nt < 4; nt++) {
            int ch0 = wn * 32 + nt * 8 + (lane & 3) * 2;
            C_s[ch0       * 260 + e0]     = acc[mt][nt][0];
            C_s[(ch0 + 1) * 260 + e0]     = acc[mt][nt][1];
            C_s[ch0       * 260 + e0 + 8] = acc[mt][nt][2];
            C_s[(ch0 + 1) * 260 + e0 + 8] = acc[mt][nt][3];
        }
    }
    __syncthreads();

    // ---- LayerNorm + store: two-pass over smem ----
    if (t < MR) {
        int qi = t >> 5, e = t & 31;
        if (e < KNN) {
            float s = 0.0f, ss = 0.0f;
            #pragma unroll
            for (int i = 0; i < 128; i++) {
                float v = C_s[i * 260 + t];
                s += v; ss += v * v;
            }
            float mu   = s * (1.0f / 128.0f);
            float var  = ss * (1.0f / 128.0f) - mu * mu;
            float rstd = rsqrtf(var + 1e-5f);
            float4* dst = (float4*)(outE + ((size_t)(q0 + qi) * KNN + e) * NC);
            #pragma unroll
            for (int i = 0; i < 32; i++) {
                float4 o;
                o.x = (C_s[(4*i+0) * 260 + t] - mu) * rstd * lng[4*i+0] + lnb[4*i+0];
                o.y = (C_s[(4*i+1) * 260 + t] - mu) * rstd * lng[4*i+1] + lnb[4*i+1];
                o.z = (C_s[(4*i+2) * 260 + t] - mu) * rstd * lng[4*i+2] + lnb[4*i+2];
                o.w = (C_s[(4*i+3) * 260 + t] - mu) * rstd * lng[4*i+3] + lnb[4*i+3];
                dst[i] = o;
            }
        }
    }
}

// ---------------- launch ----------------
extern "C" void kernel_launch(void* const* d_in, const int* in_sizes, int n_in,
                              void* d_out, int out_size) {
    const float* X      = (const float*)d_in[0];
    const float* mask   = (const float*)d_in[1];
    const int*   ridx   = (const int*)  d_in[2];
    const int*   chl    = (const int*)  d_in[3];
    const float* pos_w  = (const float*)d_in[4];
    const float* pos_b  = (const float*)d_in[5];
    const float* edge_w = (const float*)d_in[6];
    const float* ln_g   = (const float*)d_in[7];
    const float* ln_b   = (const float*)d_in[8];
    float* out = (float*)d_out;
    float* outIdxF = out + (size_t)NQ * KNN * NC;

    static int attr_set = 0;
    if (!attr_set) {
        cudaFuncSetAttribute(kEdge, cudaFuncAttributeMaxDynamicSharedMemorySize, SMEM_DYN);
        attr_set = 1;
    }

    kAtoms<<<(NQ + 255) / 256, 256>>>(X);
    kPrepW<<<(NC * NK + 255) / 256, 256>>>(edge_w);
    kKnn<<<NQ, 256>>>(mask, outIdxF);
    kEdge<<<NQ / QPB, NT, SMEM_DYN>>>(ridx, chl, pos_w, pos_b, ln_g, ln_b, out);
}

// round 16
// speedup vs baseline: 3.8111x; 1.2286x over previous
#include <cuda_runtime.h>
#include <cuda_fp16.h>
#include <math.h>
#include <stdint.h>

#define BB   8
#define LL   2048
#define KNN  30
#define NQ   (BB*LL)           // 16384 queries
#define NFR  416               // real feature dim
#define NK   448               // padded K
#define NC   128               // output channels
#define QPB  8                 // queries per CTA -> M=256
#define MR   256               // edge rows per CTA
#define NT   512               // threads
#define NCHUNK 7               // K-chunks of 64
#define CHB  16384             // B half-tile bytes (128 ch x 128B)
#define ATB  32768             // A tile bytes (256 rows x 128B)

// smem layout (byte offsets from 1024-aligned base)
#define SM_A    0              // 2 bufs x 32K = 64K (fp16, unsplit)
#define SM_B    65536          // 2 bufs x (hi 16K + lo 16K) = 64K
#define SM_MISC 131072
// misc sub-offsets (bytes from SM_MISC)
#define MS_AJ   0              // 256*15*4 = 15360
#define MS_AI   15360          // 120*4 -> pad 480
#define MS_DN   15840          // 256*4
#define MS_JS   16864          // 256*4
#define MS_DIDX 17888          // 256*4
#define MS_LNG  18912          // 128*4
#define MS_LNB  19424          // 128*4
#define MS_END  19936
#define SMEM_DYN (1024 + SM_MISC + MS_END)

// ---------------- scratch ----------------
__device__ float  g_atoms[NQ*15];
__device__ float4 g_ca[NQ];
__device__ int    g_eidx [NQ*KNN];
__device__ float  g_dn   [NQ*KNN];
__device__ uint4  g_wPack4[2*NCHUNK*(CHB/16)];   // [hi|lo][chunk][swizzled 128x128B]

__constant__ int c_pa[24] = {0,2,3,4,1,1,1,1,0,0,0,4,4,3,0,2,3,4,2,3,4,2,3,2};
__constant__ int c_pb[24] = {0,2,3,4,0,2,3,4,2,3,4,2,3,2,1,1,1,1,0,0,0,4,4,3};

// ---------------- helpers ----------------
__device__ __forceinline__ uint32_t smem_u32(const void* p){
    uint32_t a;
    asm("{ .reg .u64 t; cvta.to.shared.u64 t, %1; cvt.u32.u64 %0, t; }" : "=r"(a) : "l"(p));
    return a;
}
__device__ __forceinline__ uint32_t sw128(uint32_t off){ return off ^ ((off >> 3) & 0x70); }

__device__ __forceinline__ void ldsm_x4(uint32_t& r0, uint32_t& r1, uint32_t& r2, uint32_t& r3, uint32_t addr){
    asm volatile("ldmatrix.sync.aligned.m8n8.x4.shared.b16 {%0,%1,%2,%3}, [%4];"
                 : "=r"(r0), "=r"(r1), "=r"(r2), "=r"(r3) : "r"(addr));
}
__device__ __forceinline__ void mma16816(float* c,
    uint32_t a0, uint32_t a1, uint32_t a2, uint32_t a3, uint32_t b0, uint32_t b1){
    asm volatile("mma.sync.aligned.m16n8k16.row.col.f32.f16.f16.f32 "
                 "{%0,%1,%2,%3}, {%4,%5,%6,%7}, {%8,%9}, {%0,%1,%2,%3};"
                 : "+f"(c[0]), "+f"(c[1]), "+f"(c[2]), "+f"(c[3])
                 : "r"(a0), "r"(a1), "r"(a2), "r"(a3), "r"(b0), "r"(b1));
}
__device__ __forceinline__ void cp16(uint32_t dst, const void* src){
    asm volatile("cp.async.cg.shared.global [%0], [%1], 16;" :: "r"(dst), "l"(src));
}
__device__ __forceinline__ void cp_commit(){ asm volatile("cp.async.commit_group;" ::: "memory"); }
template<int N> __device__ __forceinline__ void cp_wait(){
    asm volatile("cp.async.wait_group %0;" :: "n"(N) : "memory");
}
__device__ __forceinline__ unsigned long long umin64(unsigned long long a, unsigned long long b){
    return a < b ? a : b;
}

// ---------------- kernel A: atoms + virtual Cb ----------------
__global__ void kAtoms(const float* __restrict__ X) {
    int q = blockIdx.x * blockDim.x + threadIdx.x;
    if (q >= NQ) return;
    const float* x = X + (size_t)q * 12;
    float Nx=x[0],  Ny=x[1],  Nz=x[2];
    float Ax=x[3],  Ay=x[4],  Az=x[5];
    float Cx=x[6],  Cy=x[7],  Cz=x[8];
    float Ox=x[9],  Oy=x[10], Oz=x[11];
    float bx=Ax-Nx, by=Ay-Ny, bz=Az-Nz;
    float cx=Cx-Ax, cy=Cy-Ay, cz=Cz-Az;
    float ax = by*cz - bz*cy;
    float ay = bz*cx - bx*cz;
    float az = bx*cy - by*cx;
    float Bx = -0.58273431f*ax + 0.56802827f*bx - 0.54067466f*cx + Ax;
    float By = -0.58273431f*ay + 0.56802827f*by - 0.54067466f*cy + Ay;
    float Bz = -0.58273431f*az + 0.56802827f*bz - 0.54067466f*cz + Az;
    float* o = g_atoms + (size_t)q * 15;
    o[0]=Nx; o[1]=Ny; o[2]=Nz;
    o[3]=Ax; o[4]=Ay; o[5]=Az;
    o[6]=Cx; o[7]=Cy; o[8]=Cz;
    o[9]=Ox; o[10]=Oy; o[11]=Oz;
    o[12]=Bx; o[13]=By; o[14]=Bz;
    g_ca[q] = make_float4(Ax, Ay, Az, 0.0f);
}

// ---------------- kernel W: split edge_w into swizzled fp16 hi/lo tiles ----
__global__ void kPrepW(const float* __restrict__ ew) {
    int idx = blockIdx.x * blockDim.x + threadIdx.x;
    if (idx >= NC * NK) return;
    int ch = idx / NK, k = idx % NK;
    float v = (k < NFR) ? ew[(size_t)ch * NFR + k] : 0.0f;
    __half hi = __float2half_rn(v);
    float lo = v - __half2float(hi);
    __half lb = __float2half_rn(lo);
    int c = k >> 6, kk = k & 63;
    uint32_t sw = sw128((uint32_t)(ch * 128 + kk * 2));
    unsigned char* base = (unsigned char*)g_wPack4;
    *(unsigned short*)(base + (size_t)c * CHB + sw) = __half_as_ushort(hi);
    *(unsigned short*)(base + (size_t)(NCHUNK + c) * CHB + sw) = __half_as_ushort(lb);
}

// ---------------- kernel B: hierarchical kNN ------------------------------
__global__ void kKnn(const float* __restrict__ mask, float* __restrict__ outIdxF) {
    __shared__ float Dv[LL];
    __shared__ unsigned long long P[LL];
    __shared__ unsigned long long gmin[64];
    __shared__ float wmax[8];

    const int q = blockIdx.x;
    const int b = q / LL;
    const int t = threadIdx.x;
    const int lane = t & 31, wid = t >> 5;

    const float mi = mask[q];
    const float4 ca = g_ca[q];

    float lmax = 0.0f;
    #pragma unroll
    for (int i = 0; i < 8; i++) {
        int j = t + i * 256;
        float4 cj = g_ca[b * LL + j];
        float dx = ca.x - cj.x, dy = ca.y - cj.y, dz = ca.z - cj.z;
        float d2 = dx*dx + dy*dy + dz*dz;
        float mj = mask[b * LL + j];
        float D  = mi * mj * sqrtf(d2 + 1e-6f);
        Dv[j] = D;
        lmax = fmaxf(lmax, D);
    }
    #pragma unroll
    for (int o = 16; o > 0; o >>= 1) lmax = fmaxf(lmax, __shfl_xor_sync(0xffffffffu, lmax, o));
    if (lane == 0) wmax[wid] = lmax;
    __syncthreads();
    float Dmax = wmax[0];
    #pragma unroll
    for (int w = 1; w < 8; w++) Dmax = fmaxf(Dmax, wmax[w]);

    #pragma unroll
    for (int i = 0; i < 8; i++) {
        int j = t + i * 256;
        float m2  = mi * mask[b * LL + j];
        float adj = Dv[j] + (1.0f - m2) * Dmax;
        P[j] = ((unsigned long long)__float_as_uint(adj) << 32) | (unsigned)j;
    }
    __syncthreads();

    #pragma unroll
    for (int i = 0; i < 8; i++) {
        int g = wid * 8 + i;
        unsigned long long v = P[g * 32 + lane];
        #pragma unroll
        for (int o = 16; o > 0; o >>= 1)
            v = umin64(v, __shfl_xor_sync(0xffffffffu, v, o));
        if (lane == 0) gmin[g] = v;
    }
    __syncthreads();

    if (wid == 0) {
        for (int k = 0; k < KNN; k++) {
            unsigned long long x = umin64(gmin[lane], gmin[lane + 32]);
            #pragma unroll
            for (int o = 16; o > 0; o >>= 1)
                x = umin64(x, __shfl_xor_sync(0xffffffffu, x, o));
            int j = (int)(x & 0xFFFFFFFFull);
            if (lane == 0) {
                g_eidx[(size_t)q * KNN + k] = j;
                g_dn  [(size_t)q * KNN + k] = __uint_as_float((unsigned)(x >> 32));
                outIdxF[(size_t)q * KNN + k] = (float)j;
            }
            int g = j >> 5;
            unsigned long long v = P[g * 32 + lane];
            if (g * 32 + lane == j) { v = 0xFFFFFFFFFFFFFFFFull; P[j] = 0xFFFFFFFFFFFFFFFFull; }
            #pragma unroll
            for (int o = 16; o > 0; o >>= 1)
                v = umin64(v, __shfl_xor_sync(0xffffffffu, v, o));
            if (lane == 0) gmin[g] = v;
            __syncwarp();
        }
    }
}

// ---------------- kernel C: features -> HMMA GEMM -> LayerNorm ------------
__device__ __forceinline__ void stageB(int t, int c, int buf, uint32_t base) {
    uint32_t dsth = base + SM_B + (uint32_t)buf * 32768u;
    const uint4* sh = g_wPack4 + (size_t)c * (CHB/16);
    const uint4* sl = g_wPack4 + (size_t)(NCHUNK + c) * (CHB/16);
    #pragma unroll
    for (int i = 0; i < 2; i++) {
        int idx = t + i * NT;
        cp16(dsth + (uint32_t)idx * 16u, (const void*)(sh + idx));
        cp16(dsth + 16384u + (uint32_t)idx * 16u, (const void*)(sl + idx));
    }
}

__global__ void __launch_bounds__(NT, 1) kEdge(
    const int*   __restrict__ ridx,
    const int*   __restrict__ chl,
    const float* __restrict__ pos_w,
    const float* __restrict__ pos_b,
    const float* __restrict__ ln_g,
    const float* __restrict__ ln_b,
    float*       __restrict__ outE)
{
    extern __shared__ unsigned char smraw[];
    const uint32_t base0 = smem_u32(smraw);
    const uint32_t base  = (base0 + 1023u) & ~1023u;
    unsigned char* sm    = smraw + (base - base0);

    unsigned char* miscb = sm + SM_MISC;
    float* aj   = (float*)(miscb + MS_AJ);
    float* ai   = (float*)(miscb + MS_AI);
    float* dn_s = (float*)(miscb + MS_DN);
    int*   j_s  = (int*)  (miscb + MS_JS);
    int*   didx = (int*)  (miscb + MS_DIDX);
    float* lng  = (float*)(miscb + MS_LNG);
    float* lnb  = (float*)(miscb + MS_LNB);

    const int t  = threadIdx.x;
    const int q0 = blockIdx.x * QPB;
    const int b  = q0 / LL;

    // per-edge metadata (256 rows)
    if (t < MR) {
        int qi = t >> 5, e = t & 31;
        int q = q0 + qi;
        if (e < KNN) {
            int j = g_eidx[(size_t)q * KNN + e];
            j_s[t]  = j;
            dn_s[t] = g_dn[(size_t)q * KNN + e];
            int off  = ridx[q] - ridx[b * LL + j];
            int same = (chl[q] == chl[b * LL + j]);
            int d;
            if (same) { d = off + 32; d = d < 0 ? 0 : (d > 64 ? 64 : d); }
            else d = 65;
            didx[t] = d;
        } else { j_s[t] = 0; dn_s[t] = 0.0f; didx[t] = 0; }
    }
    if (t >= 256 && t < 384) { lng[t - 256] = ln_g[t - 256]; lnb[t - 256] = ln_b[t - 256]; }
    if (t >= 384 && t < 384 + QPB * 15) {
        int u = t - 384;
        ai[u] = g_atoms[(size_t)(q0 + u / 15) * 15 + (u % 15)];
    }
    __syncthreads();

    for (int idx = t; idx < MR * 15; idx += NT) {
        int er = idx / 15;
        aj[idx] = g_atoms[((size_t)b * LL + j_s[er]) * 15 + (idx % 15)];
    }

    // prefetch B chunk 0 into buf 0
    stageB(t, 0, 0, base);
    cp_commit();
    __syncthreads();

    const int wid = t >> 5, lane = t & 31;
    const int wm = wid & 3, wn = wid >> 2;     // warp grid: 4M x 4N
    const int lr = lane & 15, lh = lane >> 4;

    float acc[4][4][4];
    #pragma unroll
    for (int mt = 0; mt < 4; mt++)
        #pragma unroll
        for (int nt = 0; nt < 4; nt++)
            #pragma unroll
            for (int i = 0; i < 4; i++) acc[mt][nt][i] = 0.0f;

    // feature chunk cc -> A buffer abuf (256 rows x 64 K, fp16, swizzled)
    auto computeA = [&](int cc, int abuf) {
        unsigned char* Ah = sm + SM_A + (uint32_t)abuf * ATB;
        #pragma unroll
        for (int it = 0; it < 2; it++) {
            int task = t + it * NT;             // 1024 tasks: 4 groups x 256 rows
            int gl   = task >> 8, row = task & 255;
            int g    = cc * 4 + gl;
            int qi   = row >> 5, e = row & 31;
            float v[16];
            bool valid = (e < KNN) && (g < 26);
            if (valid) {
                if (g == 0) {
                    int d = didx[row];
                    #pragma unroll
                    for (int r = 0; r < 16; r++)
                        v[r] = __ldg(pos_w + r * 66 + d) + __ldg(pos_b + r);
                } else {
                    float D;
                    int s = g - 1;
                    if (s == 0) D = dn_s[row];
                    else {
                        int p = s - 1;
                        int a3 = c_pa[p] * 3, b3 = c_pb[p] * 3;
                        const float* aiq = ai + qi * 15;
                        const float* ajr = aj + row * 15;
                        float dx = aiq[a3+0] - ajr[b3+0];
                        float dy = aiq[a3+1] - ajr[b3+1];
                        float dz = aiq[a3+2] - ajr[b3+2];
                        D = sqrtf(dx*dx + dy*dy + dz*dz + 1e-6f);
                    }
                    #pragma unroll
                    for (int r = 0; r < 16; r++) {
                        float u = (D - (2.0f + (20.0f/15.0f) * (float)r)) * 0.8f;
                        v[r] = __expf(-u * u);
                    }
                }
            } else {
                #pragma unroll
                for (int r = 0; r < 16; r++) v[r] = 0.0f;
            }
            uint32_t hw[8];
            #pragma unroll
            for (int i = 0; i < 8; i++)
                asm("cvt.rn.f16x2.f32 %0, %1, %2;" : "=r"(hw[i]) : "f"(v[2*i+1]), "f"(v[2*i]));
            uint32_t off = (uint32_t)(row * 128 + gl * 32);
            uint32_t s0 = sw128(off), s1 = sw128(off + 16);
            *(uint4*)(Ah + s0) = make_uint4(hw[0], hw[1], hw[2], hw[3]);
            *(uint4*)(Ah + s1) = make_uint4(hw[4], hw[5], hw[6], hw[7]);
        }
    };

    computeA(0, 0);
    __syncthreads();

    for (int c = 0; c < NCHUNK; c++) {
        const int buf = c & 1;
        if (c < 6) { stageB(t, c + 1, buf ^ 1, base); cp_commit(); }
        if (c < 6) cp_wait<1>(); else cp_wait<0>();

        const uint32_t Bh  = base + SM_B + (uint32_t)buf * 32768u;
        const uint32_t Bl  = Bh + 16384u;
        const uint32_t Ahb = base + SM_A + (uint32_t)buf * ATB;

        #pragma unroll
        for (int ks = 0; ks < 4; ks++) {
            uint32_t bh[8], bl[8];
            #pragma unroll
            for (int p = 0; p < 2; p++) {
                int ch = wn * 32 + p * 16 + lr;
                uint32_t off = (uint32_t)(ch * 128 + ks * 32 + lh * 16);
                uint32_t sw = sw128(off);
                ldsm_x4(bh[p*4+0], bh[p*4+1], bh[p*4+2], bh[p*4+3], Bh + sw);
                ldsm_x4(bl[p*4+0], bl[p*4+1], bl[p*4+2], bl[p*4+3], Bl + sw);
            }
            #pragma unroll
            for (int mt = 0; mt < 4; mt++) {
                int row = wm * 64 + mt * 16 + lr;
                uint32_t off = (uint32_t)(row * 128 + ks * 32 + lh * 16);
                uint32_t sw = sw128(off);
                uint32_t a0, a1, a2, a3;
                ldsm_x4(a0, a1, a2, a3, Ahb + sw);
                #pragma unroll
                for (int nt = 0; nt < 4; nt++) {
                    uint32_t b0 = bh[(nt >> 1) * 4 + (nt & 1)];
                    uint32_t b1 = bh[(nt >> 1) * 4 + 2 + (nt & 1)];
                    mma16816(acc[mt][nt], a0, a1, a2, a3, b0, b1);
                }
                #pragma unroll
                for (int nt = 0; nt < 4; nt++) {
                    uint32_t b0 = bl[(nt >> 1) * 4 + (nt & 1)];
                    uint32_t b1 = bl[(nt >> 1) * 4 + 2 + (nt & 1)];
                    mma16816(acc[mt][nt], a0, a1, a2, a3, b0, b1);
                }
            }
        }

        if (c < 6) computeA(c + 1, buf ^ 1);
        __syncthreads();
    }

    // ---- epilogue: acc -> smem [ch][edge] stride 260 (conflict-free) ----
    float* C_s = (float*)sm;
    #pragma unroll
    for (int mt = 0; mt < 4; mt++) {
        int e0 = wm * 64 + mt * 16 + (lane >> 2);
        #pragma unroll
        for (int nt = 0; nt < 4; nt++) {
            int ch0 = wn * 32 + nt * 8 + (lane & 3) * 2;
            C_s[ch0       * 260 + e0]     = acc[mt][nt][0];
            C_s[(ch0 + 1) * 260 + e0]     = acc[mt][nt][1];
            C_s[ch0       * 260 + e0 + 8] = acc[mt][nt][2];
            C_s[(ch0 + 1) * 260 + e0 + 8] = acc[mt][nt][3];
        }
    }
    __syncthreads();

    // ---- LayerNorm + store: two-pass over smem ----
    if (t < MR) {
        int qi = t >> 5, e = t & 31;
        if (e < KNN) {
            float s = 0.0f, ss = 0.0f;
            #pragma unroll
            for (int i = 0; i < 128; i++) {
                float v = C_s[i * 260 + t];
                s += v; ss += v * v;
            }
            float mu   = s * (1.0f / 128.0f);
            float var  = ss * (1.0f / 128.0f) - mu * mu;
            float rstd = rsqrtf(var + 1e-5f);
            float4* dst = (float4*)(outE + ((size_t)(q0 + qi) * KNN + e) * NC);
            #pragma unroll
            for (int i = 0; i < 32; i++) {
                float4 o;
                o.x = (C_s[(4*i+0) * 260 + t] - mu) * rstd * lng[4*i+0] + lnb[4*i+0];
                o.y = (C_s[(4*i+1) * 260 + t] - mu) * rstd * lng[4*i+1] + lnb[4*i+1];
                o.z = (C_s[(4*i+2) * 260 + t] - mu) * rstd * lng[4*i+2] + lnb[4*i+2];
                o.w = (C_s[(4*i+3) * 260 + t] - mu) * rstd * lng[4*i+3] + lnb[4*i+3];
                dst[i] = o;
            }
        }
    }
}

// ---------------- launch ----------------
extern "C" void kernel_launch(void* const* d_in, const int* in_sizes, int n_in,
                              void* d_out, int out_size) {
    const float* X      = (const float*)d_in[0];
    const float* mask   = (const float*)d_in[1];
    const int*   ridx   = (const int*)  d_in[2];
    const int*   chl    = (const int*)  d_in[3];
    const float* pos_w  = (const float*)d_in[4];
    const float* pos_b  = (const float*)d_in[5];
    const float* edge_w = (const float*)d_in[6];
    const float* ln_g   = (const float*)d_in[7];
    const float* ln_b   = (const float*)d_in[8];
    float* out = (float*)d_out;
    float* outIdxF = out + (size_t)NQ * KNN * NC;

    static int attr_set = 0;
    if (!attr_set) {
        cudaFuncSetAttribute(kEdge, cudaFuncAttributeMaxDynamicSharedMemorySize, SMEM_DYN);
        attr_set = 1;
    }

    kAtoms<<<(NQ + 255) / 256, 256>>>(X);
    kPrepW<<<(NC * NK + 255) / 256, 256>>>(edge_w);
    kKnn<<<NQ, 256>>>(mask, outIdxF);
    kEdge<<<NQ / QPB, NT, SMEM_DYN>>>(ridx, chl, pos_w, pos_b, ln_g, ln_b, out);
}